// round 2
// baseline (speedup 1.0000x reference)
#include <cuda_runtime.h>
#include <cuda_bf16.h>
#include <math.h>

// Problem constants (fixed by setup_inputs)
#define BATCH 8192
#define KN 8
#define TT 20
#define FF 7
#define HH 128
#define NB 32          // sequences per LSTM block
#define PRED 25

// ---------------- scratch (device globals; no allocations allowed) ----------
__device__ float g_ht[BATCH * HH];              // target encoder h
__device__ float g_hn[BATCH * KN * HH];         // neighbor encoder h
__device__ float g_y1[BATCH * 64 * 64];         // conv1 output (relu'd) [B,64ch,64px]
__device__ float g_pool[BATCH * 32];            // maxpooled conv2 [B,32]
__device__ float g_fused[BATCH * HH];           // fusion output [B,128]

// ---------------- generic LSTM encoder ------------------------------------
// Block: 512 threads = 4 gates x 128 hidden. Handles NB=32 sequences.
// gx computed on the fly (x + w_ih in shared), w_hh streamed from L1/L2.
__global__ __launch_bounds__(512) void lstm_kernel(
    const float* __restrict__ x,      // [nseq, TT, FF]
    const float* __restrict__ w_ih,   // [4H, FF]
    const float* __restrict__ w_hh,   // [4H, H]
    const float* __restrict__ b_ih,
    const float* __restrict__ b_hh,
    float* __restrict__ h_out)        // [nseq, H]
{
    extern __shared__ float sm[];
    float* s_x   = sm;                          // NB*TT*FF = 4480
    float* s_h   = s_x + NB * TT * FF;          // NB*H = 4096 (16B aligned: 4480*4=17920)
    float* s_c   = s_h + NB * HH;               // 4096
    float* s_g   = s_c + NB * HH;               // 4*NB*H = 16384
    float* s_wih = s_g + 4 * NB * HH;           // 4H*FF = 3584
    float* s_b   = s_wih + 4 * HH * FF;         // 512

    const int tid = threadIdx.x;
    const int g = tid >> 7;
    const int j = tid & 127;
    const int seq0 = blockIdx.x * NB;

    for (int i = tid; i < 4 * HH * FF; i += 512) s_wih[i] = w_ih[i];
    s_b[tid] = b_ih[tid] + b_hh[tid];
    for (int i = tid; i < NB * TT * FF; i += 512) s_x[i] = x[(long)seq0 * (TT * FF) + i];
    for (int i = tid; i < NB * HH; i += 512) { s_h[i] = 0.f; s_c[i] = 0.f; }
    __syncthreads();

    const int row = g * HH + j;
    float wi[FF];
#pragma unroll
    for (int f = 0; f < FF; f++) wi[f] = s_wih[row * FF + f];
    const float bb = s_b[row];
    const float4* wrow = (const float4*)(w_hh + row * HH);

    for (int t = 0; t < TT; t++) {
        float acc[NB];
#pragma unroll
        for (int s = 0; s < NB; s++) {
            const float* xs = s_x + s * (TT * FF) + t * FF;
            float a = bb;
#pragma unroll
            for (int f = 0; f < FF; f++) a = fmaf(wi[f], xs[f], a);
            acc[s] = a;
        }
        const float4* h4 = (const float4*)s_h;
#pragma unroll 2
        for (int kk = 0; kk < HH / 4; kk++) {
            float4 w = wrow[kk];
#pragma unroll
            for (int s = 0; s < NB; s++) {
                float4 hv = h4[s * (HH / 4) + kk];
                acc[s] = fmaf(w.x, hv.x, acc[s]);
                acc[s] = fmaf(w.y, hv.y, acc[s]);
                acc[s] = fmaf(w.z, hv.z, acc[s]);
                acc[s] = fmaf(w.w, hv.w, acc[s]);
            }
        }
#pragma unroll
        for (int s = 0; s < NB; s++) {
            float v = acc[s];
            v = (g == 2) ? tanhf(v) : 1.f / (1.f + __expf(-v));
            s_g[(g * NB + s) * HH + j] = v;
        }
        __syncthreads();
        // update: gate-group g handles sequences [g*8, g*8+8)
#pragma unroll
        for (int ss = 0; ss < NB / 4; ss++) {
            int s = g * (NB / 4) + ss;
            float iv = s_g[(0 * NB + s) * HH + j];
            float fv = s_g[(1 * NB + s) * HH + j];
            float gv = s_g[(2 * NB + s) * HH + j];
            float ov = s_g[(3 * NB + s) * HH + j];
            float c = fmaf(fv, s_c[s * HH + j], iv * gv);
            s_c[s * HH + j] = c;
            s_h[s * HH + j] = ov * tanhf(c);
        }
        __syncthreads();
    }
#pragma unroll
    for (int ss = 0; ss < NB / 4; ss++) {
        int s = g * (NB / 4) + ss;
        h_out[(long)(seq0 + s) * HH + j] = s_h[s * HH + j];
    }
}

// ---------------- conv1: sparse social grid -> [B,64,8,8] (relu) -----------
// Occupied cells: target @(4,4); neighbor k @ ((k+1)/8, (k+1)%8).
__global__ __launch_bounds__(256) void conv1_kernel(
    const float* __restrict__ w1,    // [64,128,3,3]
    const float* __restrict__ b1)    // [64]
{
    extern __shared__ float sm[];    // s_v[8b][9cell][129]
    const int tid = threadIdx.x;
    const int b0 = blockIdx.x * 8;

    for (int i = tid; i < 8 * 9 * 128; i += 256) {
        int b = i / 1152, r = i % 1152, cell = r >> 7, c = r & 127;
        float v = (cell == 0) ? g_ht[(b0 + b) * HH + c]
                              : g_hn[((b0 + b) * KN + cell - 1) * HH + c];
        sm[(b * 9 + cell) * 129 + c] = v;
    }
    __syncthreads();

    const int CY[9] = {4, 0, 0, 0, 0, 0, 0, 0, 1};
    const int CX[9] = {4, 1, 2, 3, 4, 5, 6, 7, 0};
    const int b = tid & 7;
    const int o0 = tid >> 3;             // 0..31
    const float* vbase = sm + b * 9 * 129;

    for (int oi = 0; oi < 2; oi++) {
        int o = o0 + oi * 32;
        float bias = __ldg(b1 + o);
        const float* wbase = w1 + o * 1152;
        for (int p = 0; p < 8; p++) {
            float acc8[8];
#pragma unroll
            for (int q = 0; q < 8; q++) acc8[q] = bias;
#pragma unroll
            for (int ci = 0; ci < 9; ci++) {
                int dy = CY[ci] - p;
                if (dy < -1 || dy > 1) continue;
                const float* vp = vbase + ci * 129;
#pragma unroll
                for (int dq = -1; dq <= 1; dq++) {
                    int q = CX[ci] + dq;
                    if (q < 0 || q > 7) continue;
                    int tap = (dy + 1) * 3 + (CX[ci] - q + 1);
                    const float* wp = wbase + tap;
                    float s2 = 0.f;
#pragma unroll 4
                    for (int c = 0; c < 128; c++) s2 = fmaf(__ldg(wp + c * 9), vp[c], s2);
                    acc8[q] += s2;
                }
            }
            float4 v0 = make_float4(fmaxf(acc8[0], 0.f), fmaxf(acc8[1], 0.f),
                                    fmaxf(acc8[2], 0.f), fmaxf(acc8[3], 0.f));
            float4 v1 = make_float4(fmaxf(acc8[4], 0.f), fmaxf(acc8[5], 0.f),
                                    fmaxf(acc8[6], 0.f), fmaxf(acc8[7], 0.f));
            float4* dst = (float4*)(g_y1 + ((long)(b0 + b) * 64 + o) * 64 + p * 8);
            dst[0] = v0;
            dst[1] = v1;
        }
    }
}

// ---------------- conv2 + relu + global maxpool -> g_pool [B,32] ------------
__global__ __launch_bounds__(512) void conv2_kernel(
    const float* __restrict__ w2,    // [32,64,3,3]
    const float* __restrict__ b2)    // [32]
{
    extern __shared__ float sm[];
    float* s_y = sm;                 // 2*64*64 = 8192
    float* s_w = sm + 8192;          // 32 rows * 577 (padded)
    const int tid = threadIdx.x;
    const int b0 = blockIdx.x * 2;

    for (int i = tid; i < 8192; i += 512) s_y[i] = g_y1[(long)b0 * 4096 + i];
    for (int i = tid; i < 32 * 576; i += 512) {
        int c2 = i / 576, r = i % 576;
        s_w[c2 * 577 + r] = w2[i];
    }
    __syncthreads();

    const int b = tid >> 8;                 // 0..1
    const int c2 = (tid >> 3) & 31;         // 0..31
    const int p = tid & 7;                  // 0..7
    float acc[8];
#pragma unroll
    for (int q = 0; q < 8; q++) acc[q] = 0.f;

    for (int ty = 0; ty < 3; ty++) {
        int ip = p + ty - 1;
        if (ip < 0 || ip > 7) continue;
        for (int c1 = 0; c1 < 64; c1++) {
            const float4* yr = (const float4*)(s_y + ((b * 64 + c1) * 64 + ip * 8));
            float4 a0 = yr[0], a1 = yr[1];
            float r[8] = {a0.x, a0.y, a0.z, a0.w, a1.x, a1.y, a1.z, a1.w};
            const float* wp = s_w + c2 * 577 + c1 * 9 + ty * 3;
            float w0 = wp[0], w1v = wp[1], w2v = wp[2];
#pragma unroll
            for (int q = 1; q < 8; q++) acc[q] = fmaf(w0, r[q - 1], acc[q]);
#pragma unroll
            for (int q = 0; q < 8; q++) acc[q] = fmaf(w1v, r[q], acc[q]);
#pragma unroll
            for (int q = 0; q < 7; q++) acc[q] = fmaf(w2v, r[q + 1], acc[q]);
        }
    }
    float bias = __ldg(b2 + c2);
    float m = 0.f;  // relu floor
#pragma unroll
    for (int q = 0; q < 8; q++) m = fmaxf(m, acc[q] + bias);
    for (int off = 4; off; off >>= 1)
        m = fmaxf(m, __shfl_xor_sync(0xffffffffu, m, off));
    if (p == 0) g_pool[(b0 + b) * 32 + c2] = m;
}

// ---------------- fusion: tanh([ht; pooled] @ fus_w^T + fus_b) --------------
__global__ __launch_bounds__(512) void fuse_kernel(
    const float* __restrict__ fw,    // [128,160]
    const float* __restrict__ fb)    // [128]
{
    extern __shared__ float sm[];
    float* s_w = sm;                 // 128*161 padded
    float* s_in = sm + 128 * 161;    // 32*160
    const int tid = threadIdx.x;
    const int b0 = blockIdx.x * 32;

    for (int i = tid; i < 128 * 160; i += 512) {
        int r = i / 160, c = i % 160;
        s_w[r * 161 + c] = fw[i];
    }
    for (int i = tid; i < 32 * 160; i += 512) {
        int s = i / 160, c = i % 160;
        s_in[i] = (c < 128) ? g_ht[(b0 + s) * HH + c] : g_pool[(b0 + s) * 32 + (c - 128)];
    }
    __syncthreads();

    const int g = tid >> 7, j = tid & 127;
    float acc[8];
    float bias = __ldg(fb + j);
#pragma unroll
    for (int ss = 0; ss < 8; ss++) acc[ss] = bias;
    for (int k = 0; k < 160; k++) {
        float w = s_w[j * 161 + k];
#pragma unroll
        for (int ss = 0; ss < 8; ss++)
            acc[ss] = fmaf(w, s_in[(g * 8 + ss) * 160 + k], acc[ss]);
    }
#pragma unroll
    for (int ss = 0; ss < 8; ss++)
        g_fused[(b0 + g * 8 + ss) * HH + j] = tanhf(acc[ss]);
}

// ---------------- autoregressive decoder (25 steps) -------------------------
__global__ __launch_bounds__(512) void dec_kernel(
    const float* __restrict__ w_ih,   // [512,2]
    const float* __restrict__ w_hh,   // [512,128]
    const float* __restrict__ b_ih,
    const float* __restrict__ b_hh,
    const float* __restrict__ out_w,  // [2,128]
    const float* __restrict__ out_b,  // [2]
    float* __restrict__ out)          // [B,25,2]
{
    extern __shared__ float sm[];
    float* s_h = sm;                  // 4096
    float* s_c = s_h + NB * HH;       // 4096
    float* s_g = s_c + NB * HH;       // 16384
    float* s_inp = s_g + 4 * NB * HH; // 64
    float* s_ow = s_inp + 64;         // 256

    const int tid = threadIdx.x;
    const int g = tid >> 7, j = tid & 127;
    const int b0 = blockIdx.x * NB;

    for (int i = tid; i < NB * HH; i += 512) {
        s_h[i] = g_fused[(long)b0 * HH + i];
        s_c[i] = 0.f;
    }
    if (tid < 64) s_inp[tid] = 0.f;
    if (tid < 256) s_ow[tid] = out_w[tid];
    __syncthreads();

    const int row = g * HH + j;
    const float bb = b_ih[row] + b_hh[row];
    const float wi0 = w_ih[row * 2];
    const float wi1 = w_ih[row * 2 + 1];
    const float ob = out_b[tid & 1];
    const float4* wrow = (const float4*)(w_hh + row * HH);

    for (int t = 0; t < PRED; t++) {
        float acc[NB];
#pragma unroll
        for (int s = 0; s < NB; s++)
            acc[s] = fmaf(wi1, s_inp[s * 2 + 1], fmaf(wi0, s_inp[s * 2], bb));
        const float4* h4 = (const float4*)s_h;
#pragma unroll 2
        for (int kk = 0; kk < HH / 4; kk++) {
            float4 w = wrow[kk];
#pragma unroll
            for (int s = 0; s < NB; s++) {
                float4 hv = h4[s * (HH / 4) + kk];
                acc[s] = fmaf(w.x, hv.x, acc[s]);
                acc[s] = fmaf(w.y, hv.y, acc[s]);
                acc[s] = fmaf(w.z, hv.z, acc[s]);
                acc[s] = fmaf(w.w, hv.w, acc[s]);
            }
        }
#pragma unroll
        for (int s = 0; s < NB; s++) {
            float v = acc[s];
            v = (g == 2) ? tanhf(v) : 1.f / (1.f + __expf(-v));
            s_g[(g * NB + s) * HH + j] = v;
        }
        __syncthreads();
#pragma unroll
        for (int ss = 0; ss < NB / 4; ss++) {
            int s = g * (NB / 4) + ss;
            float iv = s_g[(0 * NB + s) * HH + j];
            float fv = s_g[(1 * NB + s) * HH + j];
            float gv = s_g[(2 * NB + s) * HH + j];
            float ov = s_g[(3 * NB + s) * HH + j];
            float c = fmaf(fv, s_c[s * HH + j], iv * gv);
            s_c[s * HH + j] = c;
            s_h[s * HH + j] = ov * tanhf(c);
        }
        __syncthreads();
        if (tid < 64) {
            int s = tid >> 1, d = tid & 1;
            const float* hw = s_ow + d * HH;
            const float* hh = s_h + s * HH;
            float psum = ob;
#pragma unroll 8
            for (int k = 0; k < HH; k++) psum = fmaf(hw[k], hh[k], psum);
            out[(long)(b0 + s) * (PRED * 2) + t * 2 + d] = psum;
            s_inp[s * 2 + d] = psum;
        }
        __syncthreads();
    }
}

// ---------------- launch ----------------------------------------------------
extern "C" void kernel_launch(void* const* d_in, const int* in_sizes, int n_in,
                              void* d_out, int out_size)
{
    const float* target  = (const float*)d_in[0];
    const float* neigh   = (const float*)d_in[1];
    // d_in[2] neigh_spatial, d_in[3] lane: unused by reference
    const float* enc_w_ih = (const float*)d_in[4];
    const float* enc_w_hh = (const float*)d_in[5];
    const float* enc_b_ih = (const float*)d_in[6];
    const float* enc_b_hh = (const float*)d_in[7];
    const float* nb_w_ih  = (const float*)d_in[8];
    const float* nb_w_hh  = (const float*)d_in[9];
    const float* nb_b_ih  = (const float*)d_in[10];
    const float* nb_b_hh  = (const float*)d_in[11];
    const float* conv1_w  = (const float*)d_in[12];
    const float* conv1_b  = (const float*)d_in[13];
    const float* conv2_w  = (const float*)d_in[14];
    const float* conv2_b  = (const float*)d_in[15];
    const float* fus_w    = (const float*)d_in[16];
    const float* fus_b    = (const float*)d_in[17];
    const float* dec_w_ih = (const float*)d_in[18];
    const float* dec_w_hh = (const float*)d_in[19];
    const float* dec_b_ih = (const float*)d_in[20];
    const float* dec_b_hh = (const float*)d_in[21];
    const float* out_w    = (const float*)d_in[22];
    const float* out_b    = (const float*)d_in[23];
    float* out = (float*)d_out;

    const int LSTM_SMEM = (NB * TT * FF + 2 * NB * HH + 4 * NB * HH + 4 * HH * FF + 512) * 4;
    const int C1_SMEM   = 8 * 9 * 129 * 4;
    const int C2_SMEM   = (8192 + 32 * 577) * 4;
    const int FUSE_SMEM = (128 * 161 + 32 * 160) * 4;
    const int DEC_SMEM  = (2 * NB * HH + 4 * NB * HH + 64 + 256) * 4;

    cudaFuncSetAttribute(lstm_kernel, cudaFuncAttributeMaxDynamicSharedMemorySize, LSTM_SMEM);
    cudaFuncSetAttribute(conv1_kernel, cudaFuncAttributeMaxDynamicSharedMemorySize, C1_SMEM);
    cudaFuncSetAttribute(conv2_kernel, cudaFuncAttributeMaxDynamicSharedMemorySize, C2_SMEM);
    cudaFuncSetAttribute(fuse_kernel, cudaFuncAttributeMaxDynamicSharedMemorySize, FUSE_SMEM);
    cudaFuncSetAttribute(dec_kernel, cudaFuncAttributeMaxDynamicSharedMemorySize, DEC_SMEM);

    float* d_ht;    cudaGetSymbolAddress((void**)&d_ht, g_ht);
    float* d_hn;    cudaGetSymbolAddress((void**)&d_hn, g_hn);

    // target encoder: 8192 seqs
    lstm_kernel<<<BATCH / NB, 512, LSTM_SMEM>>>(target, enc_w_ih, enc_w_hh,
                                                enc_b_ih, enc_b_hh, d_ht);
    // neighbor encoder: 65536 seqs (B*K flattened)
    lstm_kernel<<<BATCH * KN / NB, 512, LSTM_SMEM>>>(neigh, nb_w_ih, nb_w_hh,
                                                     nb_b_ih, nb_b_hh, d_hn);
    // social conv stack
    conv1_kernel<<<BATCH / 8, 256, C1_SMEM>>>(conv1_w, conv1_b);
    conv2_kernel<<<BATCH / 2, 512, C2_SMEM>>>(conv2_w, conv2_b);
    // fusion
    fuse_kernel<<<BATCH / 32, 512, FUSE_SMEM>>>(fus_w, fus_b);
    // decoder
    dec_kernel<<<BATCH / NB, 512, DEC_SMEM>>>(dec_w_ih, dec_w_hh, dec_b_ih, dec_b_hh,
                                              out_w, out_b, out);
}

// round 3
// speedup vs baseline: 1.5366x; 1.5366x over previous
#include <cuda_runtime.h>
#include <math.h>

#define BATCH 8192
#define KN 8
#define TT 20
#define FF 7
#define HH 128
#define NB 32
#define PRED 25
#define TBLK (BATCH/NB)   // 256 target-encoder blocks

typedef unsigned long long u64;

// ---------------- f32x2 helpers (sm_100+ packed fp32 FMA) -------------------
__device__ __forceinline__ void fma2(u64 &a, u64 x, u64 y){
    asm("fma.rn.f32x2 %0, %1, %2, %0;" : "+l"(a) : "l"(x), "l"(y));
}
__device__ __forceinline__ u64 pk(float lo, float hi){
    u64 r; asm("mov.b64 %0, {%1,%2};" : "=l"(r) : "f"(lo), "f"(hi)); return r;
}
__device__ __forceinline__ float upsum(u64 a){
    float lo, hi; asm("mov.b64 {%0,%1}, %2;" : "=f"(lo), "=f"(hi) : "l"(a));
    return lo + hi;
}
__device__ __forceinline__ float2 up2(u64 a){
    float lo, hi; asm("mov.b64 {%0,%1}, %2;" : "=f"(lo), "=f"(hi) : "l"(a));
    return make_float2(lo, hi);
}
__device__ __forceinline__ float sigf(float v){ return 1.f/(1.f + __expf(-v)); }

// ---------------- scratch ----------------------------------------------------
__device__ float g_ht[BATCH * HH];
__device__ float g_hn[BATCH * KN * HH];
__device__ float g_y1[BATCH * 64 * 64];
__device__ float g_pool[BATCH * 32];
__device__ float g_fused[BATCH * HH];
__device__ float g_wte[4 * HH * HH];   // transposed enc w_hh
__device__ float g_wtn[4 * HH * HH];   // transposed nb  w_hh
__device__ float g_wtd[4 * HH * HH];   // transposed dec w_hh

// ---------------- w_hh transpose: [row][k] -> [kk][row][4] ------------------
__global__ void transpose_kernel(const float* __restrict__ w, float* __restrict__ wt){
    int i = blockIdx.x * 256 + threadIdx.x;   // 65536 elements
    int row = i >> 7, k = i & 127;
    int kk = k >> 2, r = k & 3;
    wt[(((kk << 9) + row) << 2) + r] = w[i];
}

// ---------------- merged encoder (target + neighbor) ------------------------
__global__ __launch_bounds__(512) void enc_kernel(
    const float* __restrict__ tgt_x, const float* __restrict__ nb_x,
    const float* __restrict__ e_wih, const float* __restrict__ n_wih,
    const float* __restrict__ e_bi,  const float* __restrict__ e_bh,
    const float* __restrict__ n_bi,  const float* __restrict__ n_bh)
{
    extern __shared__ float sm[];
    float* s_x   = sm;                       // NB*TT*FF = 4480
    float* s_h   = s_x + NB * TT * FF;       // 4096
    float* s_c   = s_h + NB * HH;            // 4096
    float* s_g   = s_c + NB * HH;            // 16384
    float* s_wih = s_g + 4 * NB * HH;        // 3584
    float* s_b   = s_wih + 4 * HH * FF;      // 512

    const int tid = threadIdx.x;
    const int g = tid >> 7;
    const int j = tid & 127;

    const bool is_tgt = (blockIdx.x < TBLK);
    const int seq0 = (is_tgt ? blockIdx.x : (blockIdx.x - TBLK)) * NB;
    const float* x    = is_tgt ? tgt_x : nb_x;
    const float* wih  = is_tgt ? e_wih : n_wih;
    const float* bi   = is_tgt ? e_bi  : n_bi;
    const float* bh   = is_tgt ? e_bh  : n_bh;
    const float* wt   = is_tgt ? g_wte : g_wtn;
    float* h_out      = is_tgt ? g_ht  : g_hn;

    for (int i = tid; i < 4 * HH * FF; i += 512) s_wih[i] = wih[i];
    s_b[tid] = bi[tid] + bh[tid];
    for (int i = tid; i < NB * TT * FF; i += 512) s_x[i] = x[(long)seq0 * (TT * FF) + i];
    for (int i = tid; i < NB * HH; i += 512) { s_h[i] = 0.f; s_c[i] = 0.f; }
    __syncthreads();

    const int row = g * HH + j;
    float wi[FF];
#pragma unroll
    for (int f = 0; f < FF; f++) wi[f] = s_wih[row * FF + f];
    const float bb = s_b[row];
    const ulonglong2* wt2 = (const ulonglong2*)wt;   // idx = kk*512 + row

    for (int t = 0; t < TT; t++) {
        u64 acc[NB];
#pragma unroll
        for (int s = 0; s < NB; s++) {
            const float* xs = s_x + s * (TT * FF) + t * FF;
            float a = bb;
#pragma unroll
            for (int f = 0; f < FF; f++) a = fmaf(wi[f], xs[f], a);
            acc[s] = pk(a, 0.f);
        }
        const ulonglong2* h2 = (const ulonglong2*)s_h;
#pragma unroll 2
        for (int kk = 0; kk < 32; kk++) {
            ulonglong2 wv = wt2[(kk << 9) + row];
#pragma unroll
            for (int s = 0; s < NB; s++) {
                ulonglong2 hv = h2[(s << 5) + kk];
                fma2(acc[s], wv.x, hv.x);
                fma2(acc[s], wv.y, hv.y);
            }
        }
#pragma unroll
        for (int s = 0; s < NB; s++) {
            float v = upsum(acc[s]);
            v = (g == 2) ? tanhf(v) : sigf(v);
            s_g[(g * NB + s) * HH + j] = v;
        }
        __syncthreads();
#pragma unroll
        for (int ss = 0; ss < NB / 4; ss++) {
            int s = g * (NB / 4) + ss;
            float iv = s_g[(0 * NB + s) * HH + j];
            float fv = s_g[(1 * NB + s) * HH + j];
            float gv = s_g[(2 * NB + s) * HH + j];
            float ov = s_g[(3 * NB + s) * HH + j];
            float c = fmaf(fv, s_c[s * HH + j], iv * gv);
            s_c[s * HH + j] = c;
            s_h[s * HH + j] = ov * tanhf(c);
        }
        __syncthreads();
    }
#pragma unroll
    for (int ss = 0; ss < NB / 4; ss++) {
        int s = g * (NB / 4) + ss;
        h_out[(long)(seq0 + s) * HH + j] = s_h[s * HH + j];
    }
}

// ---------------- conv1: sparse social grid, weights staged in smem ---------
// smem: v[8][9][132] + w[32][9][132] (w transposed to [o][tap][c], c-contig)
__global__ __launch_bounds__(256) void conv1_kernel(
    const float* __restrict__ w1, const float* __restrict__ b1)
{
    extern __shared__ float sm[];
    float* s_v = sm;                 // 8*9*132 = 9504
    float* s_w = sm + 8 * 9 * 132;   // 32*9*132 = 38016
    const int tid = threadIdx.x;
    const int b0 = blockIdx.x * 8;

    for (int i = tid; i < 8 * 9 * 128; i += 256) {
        int b = i / 1152, r = i % 1152, cell = r >> 7, c = r & 127;
        float v = (cell == 0) ? g_ht[(b0 + b) * HH + c]
                              : g_hn[((b0 + b) * KN + cell - 1) * HH + c];
        s_v[(b * 9 + cell) * 132 + c] = v;
    }

    const int o = tid >> 3, b = tid & 7;
    const float* vb = s_v + b * 1188;

    for (int half = 0; half < 2; half++) {
        __syncthreads();
        for (int i = tid; i < 32 * 1152; i += 256) {
            int oo = i / 1152, r = i % 1152, c = r / 9, tap = r % 9;
            s_w[oo * 1188 + tap * 132 + c] = w1[half * 32 * 1152 + i];
        }
        __syncthreads();

        const int och = half * 32 + o;
        const float bias = __ldg(b1 + och);
        const float* wb = s_w + o * 1188;
        const int CY[9] = {4, 0, 0, 0, 0, 0, 0, 0, 1};
        const int CX[9] = {4, 1, 2, 3, 4, 5, 6, 7, 0};

        for (int p = 0; p < 8; p++) {
            u64 acc[8];
#pragma unroll
            for (int q = 0; q < 8; q++) acc[q] = pk(bias, 0.f);
#pragma unroll
            for (int ci = 0; ci < 9; ci++) {
                const int cx = CX[ci];
                int dy = CY[ci] - p;
                if (dy < -1 || dy > 1) continue;
                const ulonglong2* vp  = (const ulonglong2*)(vb + ci * 132);
                const ulonglong2* wL  = (const ulonglong2*)(wb + ((dy + 1) * 3 + 2) * 132); // q=cx-1
                const ulonglong2* wC  = (const ulonglong2*)(wb + ((dy + 1) * 3 + 1) * 132); // q=cx
                const ulonglong2* wR  = (const ulonglong2*)(wb + ((dy + 1) * 3 + 0) * 132); // q=cx+1
#pragma unroll 8
                for (int cc = 0; cc < 32; cc++) {
                    ulonglong2 vv = vp[cc];
                    if (cx - 1 >= 0) {
                        ulonglong2 wv = wL[cc];
                        fma2(acc[cx - 1], wv.x, vv.x);
                        fma2(acc[cx - 1], wv.y, vv.y);
                    }
                    {
                        ulonglong2 wv = wC[cc];
                        fma2(acc[cx], wv.x, vv.x);
                        fma2(acc[cx], wv.y, vv.y);
                    }
                    if (cx + 1 <= 7) {
                        ulonglong2 wv = wR[cc];
                        fma2(acc[cx + 1], wv.x, vv.x);
                        fma2(acc[cx + 1], wv.y, vv.y);
                    }
                }
            }
            float oq[8];
#pragma unroll
            for (int q = 0; q < 8; q++) oq[q] = fmaxf(upsum(acc[q]), 0.f);
            float4* dst = (float4*)(g_y1 + ((long)(b0 + b) * 64 + och) * 64 + p * 8);
            dst[0] = make_float4(oq[0], oq[1], oq[2], oq[3]);
            dst[1] = make_float4(oq[4], oq[5], oq[6], oq[7]);
        }
    }
}

// ---------------- conv2 + relu + maxpool (f32x2, 2 channels/thread) ---------
__global__ __launch_bounds__(256) void conv2_kernel(
    const float* __restrict__ w2, const float* __restrict__ b2)
{
    extern __shared__ float sm[];
    float* s_y = sm;                 // 2*64*64 = 8192
    float* s_w = sm + 8192;          // 32*577
    const int tid = threadIdx.x;
    const int b0 = blockIdx.x * 2;

    for (int i = tid; i < 8192; i += 256) s_y[i] = g_y1[(long)b0 * 4096 + i];
    for (int i = tid; i < 32 * 576; i += 256) {
        int c2 = i / 576, r = i % 576;
        s_w[c2 * 577 + r] = w2[i];
    }
    __syncthreads();

    const int b  = tid >> 7;          // 0..1
    const int cp = (tid >> 3) & 15;   // 0..15
    const int p  = tid & 7;           // 0..7
    const int c2a = cp, c2b = cp + 16;

    u64 acca[4], accb[4];
#pragma unroll
    for (int m = 0; m < 4; m++) { acca[m] = 0ull; accb[m] = 0ull; }

    for (int ty = 0; ty < 3; ty++) {
        int ip = p + ty - 1;
        if (ip < 0 || ip > 7) continue;
        for (int c1 = 0; c1 < 64; c1++) {
            const float4* yr = (const float4*)(s_y + ((b * 64 + c1) * 64 + ip * 8));
            float4 a0 = yr[0], a1 = yr[1];
            u64 C0 = pk(a0.x, a0.y), C1 = pk(a0.z, a0.w);
            u64 C2 = pk(a1.x, a1.y), C3 = pk(a1.z, a1.w);
            u64 L0 = pk(0.f,  a0.x), L1 = pk(a0.y, a0.z);
            u64 L2 = pk(a0.w, a1.x), L3 = pk(a1.y, a1.z);
            u64 R3 = pk(a1.w, 0.f);
            const float* wpa = s_w + c2a * 577 + c1 * 9 + ty * 3;
            const float* wpb = s_w + c2b * 577 + c1 * 9 + ty * 3;
            u64 W0a = pk(wpa[0], wpa[0]), W1a = pk(wpa[1], wpa[1]), W2a = pk(wpa[2], wpa[2]);
            u64 W0b = pk(wpb[0], wpb[0]), W1b = pk(wpb[1], wpb[1]), W2b = pk(wpb[2], wpb[2]);
            fma2(acca[0], W1a, C0); fma2(acca[1], W1a, C1);
            fma2(acca[2], W1a, C2); fma2(acca[3], W1a, C3);
            fma2(acca[0], W0a, L0); fma2(acca[1], W0a, L1);
            fma2(acca[2], W0a, L2); fma2(acca[3], W0a, L3);
            fma2(acca[0], W2a, L1); fma2(acca[1], W2a, L2);
            fma2(acca[2], W2a, L3); fma2(acca[3], W2a, R3);
            fma2(accb[0], W1b, C0); fma2(accb[1], W1b, C1);
            fma2(accb[2], W1b, C2); fma2(accb[3], W1b, C3);
            fma2(accb[0], W0b, L0); fma2(accb[1], W0b, L1);
            fma2(accb[2], W0b, L2); fma2(accb[3], W0b, L3);
            fma2(accb[0], W2b, L1); fma2(accb[1], W2b, L2);
            fma2(accb[2], W2b, L3); fma2(accb[3], W2b, R3);
        }
    }
    float bia = __ldg(b2 + c2a), bib = __ldg(b2 + c2b);
    float ma = 0.f, mb = 0.f;
#pragma unroll
    for (int m = 0; m < 4; m++) {
        float2 fa = up2(acca[m]);
        float2 fb = up2(accb[m]);
        ma = fmaxf(ma, fmaxf(fa.x, fa.y) + bia);
        mb = fmaxf(mb, fmaxf(fb.x, fb.y) + bib);
    }
    for (int off = 4; off; off >>= 1) {
        ma = fmaxf(ma, __shfl_xor_sync(0xffffffffu, ma, off));
        mb = fmaxf(mb, __shfl_xor_sync(0xffffffffu, mb, off));
    }
    if (p == 0) {
        g_pool[(b0 + b) * 32 + c2a] = ma;
        g_pool[(b0 + b) * 32 + c2b] = mb;
    }
}

// ---------------- fusion ------------------------------------------------------
__global__ __launch_bounds__(512) void fuse_kernel(
    const float* __restrict__ fw, const float* __restrict__ fb)
{
    extern __shared__ float sm[];
    float* s_w = sm;                 // 128*161
    float* s_in = sm + 128 * 161;    // 32*160
    const int tid = threadIdx.x;
    const int b0 = blockIdx.x * 32;

    for (int i = tid; i < 128 * 160; i += 512) {
        int r = i / 160, c = i % 160;
        s_w[r * 161 + c] = fw[i];
    }
    for (int i = tid; i < 32 * 160; i += 512) {
        int s = i / 160, c = i % 160;
        s_in[i] = (c < 128) ? g_ht[(b0 + s) * HH + c] : g_pool[(b0 + s) * 32 + (c - 128)];
    }
    __syncthreads();

    const int g = tid >> 7, j = tid & 127;
    float acc[8];
    float bias = __ldg(fb + j);
#pragma unroll
    for (int ss = 0; ss < 8; ss++) acc[ss] = bias;
    for (int k = 0; k < 160; k++) {
        float w = s_w[j * 161 + k];
#pragma unroll
        for (int ss = 0; ss < 8; ss++)
            acc[ss] = fmaf(w, s_in[(g * 8 + ss) * 160 + k], acc[ss]);
    }
#pragma unroll
    for (int ss = 0; ss < 8; ss++)
        g_fused[(b0 + g * 8 + ss) * HH + j] = tanhf(acc[ss]);
}

// ---------------- decoder (f32x2) -------------------------------------------
__global__ __launch_bounds__(512) void dec_kernel(
    const float* __restrict__ w_ih,
    const float* __restrict__ b_ih, const float* __restrict__ b_hh,
    const float* __restrict__ out_w, const float* __restrict__ out_b,
    float* __restrict__ out)
{
    extern __shared__ float sm[];
    float* s_h = sm;                  // 4096
    float* s_c = s_h + NB * HH;       // 4096
    float* s_g = s_c + NB * HH;       // 16384
    float* s_inp = s_g + 4 * NB * HH; // 64
    float* s_ow = s_inp + 64;         // 256

    const int tid = threadIdx.x;
    const int g = tid >> 7, j = tid & 127;
    const int b0 = blockIdx.x * NB;

    for (int i = tid; i < NB * HH; i += 512) {
        s_h[i] = g_fused[(long)b0 * HH + i];
        s_c[i] = 0.f;
    }
    if (tid < 64) s_inp[tid] = 0.f;
    if (tid < 256) s_ow[tid] = out_w[tid];
    __syncthreads();

    const int row = g * HH + j;
    const float bb = b_ih[row] + b_hh[row];
    const float wi0 = w_ih[row * 2];
    const float wi1 = w_ih[row * 2 + 1];
    const float ob = out_b[tid & 1];
    const ulonglong2* wt2 = (const ulonglong2*)g_wtd;

    for (int t = 0; t < PRED; t++) {
        u64 acc[NB];
#pragma unroll
        for (int s = 0; s < NB; s++)
            acc[s] = pk(fmaf(wi1, s_inp[s * 2 + 1], fmaf(wi0, s_inp[s * 2], bb)), 0.f);
        const ulonglong2* h2 = (const ulonglong2*)s_h;
#pragma unroll 2
        for (int kk = 0; kk < 32; kk++) {
            ulonglong2 wv = wt2[(kk << 9) + row];
#pragma unroll
            for (int s = 0; s < NB; s++) {
                ulonglong2 hv = h2[(s << 5) + kk];
                fma2(acc[s], wv.x, hv.x);
                fma2(acc[s], wv.y, hv.y);
            }
        }
#pragma unroll
        for (int s = 0; s < NB; s++) {
            float v = upsum(acc[s]);
            v = (g == 2) ? tanhf(v) : sigf(v);
            s_g[(g * NB + s) * HH + j] = v;
        }
        __syncthreads();
#pragma unroll
        for (int ss = 0; ss < NB / 4; ss++) {
            int s = g * (NB / 4) + ss;
            float iv = s_g[(0 * NB + s) * HH + j];
            float fv = s_g[(1 * NB + s) * HH + j];
            float gv = s_g[(2 * NB + s) * HH + j];
            float ov = s_g[(3 * NB + s) * HH + j];
            float c = fmaf(fv, s_c[s * HH + j], iv * gv);
            s_c[s * HH + j] = c;
            s_h[s * HH + j] = ov * tanhf(c);
        }
        __syncthreads();
        if (tid < 64) {
            int s = tid >> 1, d = tid & 1;
            const float* hw = s_ow + d * HH;
            const float* hh = s_h + s * HH;
            float psum = ob;
#pragma unroll 8
            for (int k = 0; k < HH; k++) psum = fmaf(hw[k], hh[k], psum);
            out[(long)(b0 + s) * (PRED * 2) + t * 2 + d] = psum;
            s_inp[s * 2 + d] = psum;
        }
        __syncthreads();
    }
}

// ---------------- launch ------------------------------------------------------
extern "C" void kernel_launch(void* const* d_in, const int* in_sizes, int n_in,
                              void* d_out, int out_size)
{
    const float* target  = (const float*)d_in[0];
    const float* neigh   = (const float*)d_in[1];
    const float* enc_w_ih = (const float*)d_in[4];
    const float* enc_w_hh = (const float*)d_in[5];
    const float* enc_b_ih = (const float*)d_in[6];
    const float* enc_b_hh = (const float*)d_in[7];
    const float* nb_w_ih  = (const float*)d_in[8];
    const float* nb_w_hh  = (const float*)d_in[9];
    const float* nb_b_ih  = (const float*)d_in[10];
    const float* nb_b_hh  = (const float*)d_in[11];
    const float* conv1_w  = (const float*)d_in[12];
    const float* conv1_b  = (const float*)d_in[13];
    const float* conv2_w  = (const float*)d_in[14];
    const float* conv2_b  = (const float*)d_in[15];
    const float* fus_w    = (const float*)d_in[16];
    const float* fus_b    = (const float*)d_in[17];
    const float* dec_w_ih = (const float*)d_in[18];
    const float* dec_w_hh = (const float*)d_in[19];
    const float* dec_b_ih = (const float*)d_in[20];
    const float* dec_b_hh = (const float*)d_in[21];
    const float* out_w    = (const float*)d_in[22];
    const float* out_b    = (const float*)d_in[23];
    float* out = (float*)d_out;

    const int ENC_SMEM  = (NB * TT * FF + 2 * NB * HH + 4 * NB * HH + 4 * HH * FF + 512) * 4;
    const int C1_SMEM   = (8 * 9 * 132 + 32 * 9 * 132) * 4;
    const int C2_SMEM   = (8192 + 32 * 577) * 4;
    const int FUSE_SMEM = (128 * 161 + 32 * 160) * 4;
    const int DEC_SMEM  = (2 * NB * HH + 4 * NB * HH + 64 + 256) * 4;

    cudaFuncSetAttribute(enc_kernel,  cudaFuncAttributeMaxDynamicSharedMemorySize, ENC_SMEM);
    cudaFuncSetAttribute(conv1_kernel, cudaFuncAttributeMaxDynamicSharedMemorySize, C1_SMEM);
    cudaFuncSetAttribute(conv2_kernel, cudaFuncAttributeMaxDynamicSharedMemorySize, C2_SMEM);
    cudaFuncSetAttribute(fuse_kernel, cudaFuncAttributeMaxDynamicSharedMemorySize, FUSE_SMEM);
    cudaFuncSetAttribute(dec_kernel,  cudaFuncAttributeMaxDynamicSharedMemorySize, DEC_SMEM);

    float* d_wte; cudaGetSymbolAddress((void**)&d_wte, g_wte);
    float* d_wtn; cudaGetSymbolAddress((void**)&d_wtn, g_wtn);
    float* d_wtd; cudaGetSymbolAddress((void**)&d_wtd, g_wtd);

    // one-time (per launch) weight transposes for coalesced recurrent loads
    transpose_kernel<<<256, 256>>>(enc_w_hh, d_wte);
    transpose_kernel<<<256, 256>>>(nb_w_hh,  d_wtn);
    transpose_kernel<<<256, 256>>>(dec_w_hh, d_wtd);

    // merged encoders: 256 target blocks + 2048 neighbor blocks
    enc_kernel<<<TBLK + BATCH * KN / NB, 512, ENC_SMEM>>>(
        target, neigh, enc_w_ih, nb_w_ih,
        enc_b_ih, enc_b_hh, nb_b_ih, nb_b_hh);

    conv1_kernel<<<BATCH / 8, 256, C1_SMEM>>>(conv1_w, conv1_b);
    conv2_kernel<<<BATCH / 2, 256, C2_SMEM>>>(conv2_w, conv2_b);
    fuse_kernel<<<BATCH / 32, 512, FUSE_SMEM>>>(fus_w, fus_b);
    dec_kernel<<<BATCH / NB, 512, DEC_SMEM>>>(dec_w_ih, dec_b_ih, dec_b_hh,
                                              out_w, out_b, out);
}

// round 4
// speedup vs baseline: 2.0169x; 1.3126x over previous
#include <cuda_runtime.h>
#include <math.h>

#define BATCH 8192
#define KN 8
#define TT 20
#define FF 7
#define HH 128
#define NB 16          // sequences per LSTM block (v4: 2 rows/thread)
#define PRED 25
#define TBLK (BATCH/NB)   // 512 target-encoder blocks

typedef unsigned long long u64;

// ---------------- f32x2 helpers (sm_100+ packed fp32 FMA) -------------------
__device__ __forceinline__ void fma2(u64 &a, u64 x, u64 y){
    asm("fma.rn.f32x2 %0, %1, %2, %0;" : "+l"(a) : "l"(x), "l"(y));
}
__device__ __forceinline__ u64 pk(float lo, float hi){
    u64 r; asm("mov.b64 %0, {%1,%2};" : "=l"(r) : "f"(lo), "f"(hi)); return r;
}
__device__ __forceinline__ float upsum(u64 a){
    float lo, hi; asm("mov.b64 {%0,%1}, %2;" : "=f"(lo), "=f"(hi) : "l"(a));
    return lo + hi;
}
__device__ __forceinline__ float2 up2(u64 a){
    float lo, hi; asm("mov.b64 {%0,%1}, %2;" : "=f"(lo), "=f"(hi) : "l"(a));
    return make_float2(lo, hi);
}
// MUFU-based activations (abs err ~1e-7; library tanhf is ~20 inst)
__device__ __forceinline__ float fast_sig(float v){
    return __fdividef(1.f, 1.f + __expf(-v));
}
__device__ __forceinline__ float fast_tanh(float v){
    return 1.f - __fdividef(2.f, 1.f + __expf(2.f * v));
}

// ---------------- scratch ----------------------------------------------------
__device__ float g_ht[BATCH * HH];
__device__ float g_hn[BATCH * KN * HH];
__device__ float g_y1[BATCH * 64 * 64];
__device__ float g_pool[BATCH * 32];
__device__ float g_fused[BATCH * HH];
__device__ float g_wte[4 * HH * HH];   // transposed enc w_hh
__device__ float g_wtn[4 * HH * HH];   // transposed nb  w_hh
__device__ float g_wtd[4 * HH * HH];   // transposed dec w_hh

// ---------------- w_hh transpose: [row][k] -> [kk][row][4] ------------------
__global__ void transpose_kernel(const float* __restrict__ w, float* __restrict__ wt){
    int i = blockIdx.x * 256 + threadIdx.x;   // 65536 elements
    int row = i >> 7, k = i & 127;
    int kk = k >> 2, r = k & 3;
    wt[(((kk << 9) + row) << 2) + r] = w[i];
}

// ---------------- merged encoder (target + neighbor), 2 rows/thread ---------
__global__ __launch_bounds__(256, 2) void enc_kernel(
    const float* __restrict__ tgt_x, const float* __restrict__ nb_x,
    const float* __restrict__ e_wih, const float* __restrict__ n_wih,
    const float* __restrict__ e_bi,  const float* __restrict__ e_bh,
    const float* __restrict__ n_bi,  const float* __restrict__ n_bh)
{
    extern __shared__ float sm[];
    float* s_x   = sm;                       // NB*TT*FF = 2240
    float* s_h   = s_x + NB * TT * FF;       // 2048
    float* s_c   = s_h + NB * HH;            // 2048
    float* s_g   = s_c + NB * HH;            // 4*NB*HH = 8192
    float* s_wih = s_g + 4 * NB * HH;        // 3584
    float* s_b   = s_wih + 4 * HH * FF;      // 512

    const int tid = threadIdx.x;
    const int gp = tid >> 7;                 // gate pair: 0 -> gates{0,1}, 1 -> {2,3}
    const int j = tid & 127;

    const bool is_tgt = (blockIdx.x < TBLK);
    const int seq0 = (is_tgt ? blockIdx.x : (blockIdx.x - TBLK)) * NB;
    const float* x    = is_tgt ? tgt_x : nb_x;
    const float* wih  = is_tgt ? e_wih : n_wih;
    const float* bi   = is_tgt ? e_bi  : n_bi;
    const float* bh   = is_tgt ? e_bh  : n_bh;
    const float* wt   = is_tgt ? g_wte : g_wtn;
    float* h_out      = is_tgt ? g_ht  : g_hn;

    for (int i = tid; i < 4 * HH * FF; i += 256) s_wih[i] = wih[i];
    s_b[tid] = bi[tid] + bh[tid];
    s_b[tid + 256] = bi[tid + 256] + bh[tid + 256];
    for (int i = tid; i < NB * TT * FF; i += 256) s_x[i] = x[(long)seq0 * (TT * FF) + i];
    for (int i = tid; i < NB * HH; i += 256) { s_h[i] = 0.f; s_c[i] = 0.f; }
    __syncthreads();

    const int r0 = gp * 256 + j;      // gate 2*gp
    const int r1 = r0 + 128;          // gate 2*gp+1
    float wi0[FF], wi1[FF];
#pragma unroll
    for (int f = 0; f < FF; f++) { wi0[f] = s_wih[r0 * FF + f]; wi1[f] = s_wih[r1 * FF + f]; }
    const float bb0 = s_b[r0], bb1 = s_b[r1];
    const ulonglong2* wt2 = (const ulonglong2*)wt;   // idx = kk*512 + row

    for (int t = 0; t < TT; t++) {
        u64 a0[NB], a1[NB];
#pragma unroll
        for (int s = 0; s < NB; s++) {
            const float* xs = s_x + s * (TT * FF) + t * FF;
            float v0 = bb0, v1 = bb1;
#pragma unroll
            for (int f = 0; f < FF; f++) {
                float xv = xs[f];
                v0 = fmaf(wi0[f], xv, v0);
                v1 = fmaf(wi1[f], xv, v1);
            }
            a0[s] = pk(v0, 0.f);
            a1[s] = pk(v1, 0.f);
        }
        const ulonglong2* h2 = (const ulonglong2*)s_h;
#pragma unroll 2
        for (int kk = 0; kk < 32; kk++) {
            ulonglong2 w0 = wt2[(kk << 9) + r0];
            ulonglong2 w1 = wt2[(kk << 9) + r1];
#pragma unroll
            for (int s = 0; s < NB; s++) {
                ulonglong2 hv = h2[(s << 5) + kk];
                fma2(a0[s], w0.x, hv.x);
                fma2(a0[s], w0.y, hv.y);
                fma2(a1[s], w1.x, hv.x);
                fma2(a1[s], w1.y, hv.y);
            }
        }
#pragma unroll
        for (int s = 0; s < NB; s++) {
            float v0 = upsum(a0[s]);
            float v1 = upsum(a1[s]);
            // gates: 2*gp (i or g), 2*gp+1 (f or o)
            v0 = (gp == 1) ? fast_tanh(v0) : fast_sig(v0);
            v1 = fast_sig(v1);
            s_g[((2 * gp) * NB + s) * HH + j] = v0;
            s_g[((2 * gp + 1) * NB + s) * HH + j] = v1;
        }
        __syncthreads();
#pragma unroll
        for (int ss = 0; ss < NB / 2; ss++) {
            int s = gp * (NB / 2) + ss;
            float iv = s_g[(0 * NB + s) * HH + j];
            float fv = s_g[(1 * NB + s) * HH + j];
            float gv = s_g[(2 * NB + s) * HH + j];
            float ov = s_g[(3 * NB + s) * HH + j];
            float c = fmaf(fv, s_c[s * HH + j], iv * gv);
            s_c[s * HH + j] = c;
            s_h[s * HH + j] = ov * fast_tanh(c);
        }
        __syncthreads();
    }
#pragma unroll
    for (int ss = 0; ss < NB / 2; ss++) {
        int s = gp * (NB / 2) + ss;
        h_out[(long)(seq0 + s) * HH + j] = s_h[s * HH + j];
    }
}

// ---------------- conv1: sparse social grid, weights staged in smem ---------
__global__ __launch_bounds__(256) void conv1_kernel(
    const float* __restrict__ w1, const float* __restrict__ b1)
{
    extern __shared__ float sm[];
    float* s_v = sm;                 // 8*9*132 = 9504
    float* s_w = sm + 8 * 9 * 132;   // 32*9*132 = 38016
    const int tid = threadIdx.x;
    const int b0 = blockIdx.x * 8;

    for (int i = tid; i < 8 * 9 * 128; i += 256) {
        int b = i / 1152, r = i % 1152, cell = r >> 7, c = r & 127;
        float v = (cell == 0) ? g_ht[(b0 + b) * HH + c]
                              : g_hn[((b0 + b) * KN + cell - 1) * HH + c];
        s_v[(b * 9 + cell) * 132 + c] = v;
    }

    const int o = tid >> 3, b = tid & 7;
    const float* vb = s_v + b * 1188;

    for (int half = 0; half < 2; half++) {
        __syncthreads();
        for (int i = tid; i < 32 * 1152; i += 256) {
            int oo = i / 1152, r = i % 1152, c = r / 9, tap = r % 9;
            s_w[oo * 1188 + tap * 132 + c] = w1[half * 32 * 1152 + i];
        }
        __syncthreads();

        const int och = half * 32 + o;
        const float bias = __ldg(b1 + och);
        const float* wb = s_w + o * 1188;
        const int CY[9] = {4, 0, 0, 0, 0, 0, 0, 0, 1};
        const int CX[9] = {4, 1, 2, 3, 4, 5, 6, 7, 0};

        for (int p = 0; p < 8; p++) {
            u64 acc[8];
#pragma unroll
            for (int q = 0; q < 8; q++) acc[q] = pk(bias, 0.f);
#pragma unroll
            for (int ci = 0; ci < 9; ci++) {
                const int cx = CX[ci];
                int dy = CY[ci] - p;
                if (dy < -1 || dy > 1) continue;
                const ulonglong2* vp  = (const ulonglong2*)(vb + ci * 132);
                const ulonglong2* wL  = (const ulonglong2*)(wb + ((dy + 1) * 3 + 2) * 132);
                const ulonglong2* wC  = (const ulonglong2*)(wb + ((dy + 1) * 3 + 1) * 132);
                const ulonglong2* wR  = (const ulonglong2*)(wb + ((dy + 1) * 3 + 0) * 132);
#pragma unroll 8
                for (int cc = 0; cc < 32; cc++) {
                    ulonglong2 vv = vp[cc];
                    if (cx - 1 >= 0) {
                        ulonglong2 wv = wL[cc];
                        fma2(acc[cx - 1], wv.x, vv.x);
                        fma2(acc[cx - 1], wv.y, vv.y);
                    }
                    {
                        ulonglong2 wv = wC[cc];
                        fma2(acc[cx], wv.x, vv.x);
                        fma2(acc[cx], wv.y, vv.y);
                    }
                    if (cx + 1 <= 7) {
                        ulonglong2 wv = wR[cc];
                        fma2(acc[cx + 1], wv.x, vv.x);
                        fma2(acc[cx + 1], wv.y, vv.y);
                    }
                }
            }
            float oq[8];
#pragma unroll
            for (int q = 0; q < 8; q++) oq[q] = fmaxf(upsum(acc[q]), 0.f);
            float4* dst = (float4*)(g_y1 + ((long)(b0 + b) * 64 + och) * 64 + p * 8);
            dst[0] = make_float4(oq[0], oq[1], oq[2], oq[3]);
            dst[1] = make_float4(oq[4], oq[5], oq[6], oq[7]);
        }
    }
}

// ---------------- conv2 + relu + maxpool (f32x2, 2 channels/thread) ---------
__global__ __launch_bounds__(256) void conv2_kernel(
    const float* __restrict__ w2, const float* __restrict__ b2)
{
    extern __shared__ float sm[];
    float* s_y = sm;                 // 2*64*64 = 8192
    float* s_w = sm + 8192;          // 32*577
    const int tid = threadIdx.x;
    const int b0 = blockIdx.x * 2;

    for (int i = tid; i < 8192; i += 256) s_y[i] = g_y1[(long)b0 * 4096 + i];
    for (int i = tid; i < 32 * 576; i += 256) {
        int c2 = i / 576, r = i % 576;
        s_w[c2 * 577 + r] = w2[i];
    }
    __syncthreads();

    const int b  = tid >> 7;
    const int cp = (tid >> 3) & 15;
    const int p  = tid & 7;
    const int c2a = cp, c2b = cp + 16;

    u64 acca[4], accb[4];
#pragma unroll
    for (int m = 0; m < 4; m++) { acca[m] = 0ull; accb[m] = 0ull; }

    for (int ty = 0; ty < 3; ty++) {
        int ip = p + ty - 1;
        if (ip < 0 || ip > 7) continue;
        for (int c1 = 0; c1 < 64; c1++) {
            const float4* yr = (const float4*)(s_y + ((b * 64 + c1) * 64 + ip * 8));
            float4 a0 = yr[0], a1 = yr[1];
            u64 C0 = pk(a0.x, a0.y), C1 = pk(a0.z, a0.w);
            u64 C2 = pk(a1.x, a1.y), C3 = pk(a1.z, a1.w);
            u64 L0 = pk(0.f,  a0.x), L1 = pk(a0.y, a0.z);
            u64 L2 = pk(a0.w, a1.x), L3 = pk(a1.y, a1.z);
            u64 R3 = pk(a1.w, 0.f);
            const float* wpa = s_w + c2a * 577 + c1 * 9 + ty * 3;
            const float* wpb = s_w + c2b * 577 + c1 * 9 + ty * 3;
            u64 W0a = pk(wpa[0], wpa[0]), W1a = pk(wpa[1], wpa[1]), W2a = pk(wpa[2], wpa[2]);
            u64 W0b = pk(wpb[0], wpb[0]), W1b = pk(wpb[1], wpb[1]), W2b = pk(wpb[2], wpb[2]);
            fma2(acca[0], W1a, C0); fma2(acca[1], W1a, C1);
            fma2(acca[2], W1a, C2); fma2(acca[3], W1a, C3);
            fma2(acca[0], W0a, L0); fma2(acca[1], W0a, L1);
            fma2(acca[2], W0a, L2); fma2(acca[3], W0a, L3);
            fma2(acca[0], W2a, L1); fma2(acca[1], W2a, L2);
            fma2(acca[2], W2a, L3); fma2(acca[3], W2a, R3);
            fma2(accb[0], W1b, C0); fma2(accb[1], W1b, C1);
            fma2(accb[2], W1b, C2); fma2(accb[3], W1b, C3);
            fma2(accb[0], W0b, L0); fma2(accb[1], W0b, L1);
            fma2(accb[2], W0b, L2); fma2(accb[3], W0b, L3);
            fma2(accb[0], W2b, L1); fma2(accb[1], W2b, L2);
            fma2(accb[2], W2b, L3); fma2(accb[3], W2b, R3);
        }
    }
    float bia = __ldg(b2 + c2a), bib = __ldg(b2 + c2b);
    float ma = 0.f, mb = 0.f;
#pragma unroll
    for (int m = 0; m < 4; m++) {
        float2 fa = up2(acca[m]);
        float2 fb = up2(accb[m]);
        ma = fmaxf(ma, fmaxf(fa.x, fa.y) + bia);
        mb = fmaxf(mb, fmaxf(fb.x, fb.y) + bib);
    }
    for (int off = 4; off; off >>= 1) {
        ma = fmaxf(ma, __shfl_xor_sync(0xffffffffu, ma, off));
        mb = fmaxf(mb, __shfl_xor_sync(0xffffffffu, mb, off));
    }
    if (p == 0) {
        g_pool[(b0 + b) * 32 + c2a] = ma;
        g_pool[(b0 + b) * 32 + c2b] = mb;
    }
}

// ---------------- fusion ------------------------------------------------------
__global__ __launch_bounds__(512) void fuse_kernel(
    const float* __restrict__ fw, const float* __restrict__ fb)
{
    extern __shared__ float sm[];
    float* s_w = sm;                 // 128*161
    float* s_in = sm + 128 * 161;    // 32*160
    const int tid = threadIdx.x;
    const int b0 = blockIdx.x * 32;

    for (int i = tid; i < 128 * 160; i += 512) {
        int r = i / 160, c = i % 160;
        s_w[r * 161 + c] = fw[i];
    }
    for (int i = tid; i < 32 * 160; i += 512) {
        int s = i / 160, c = i % 160;
        s_in[i] = (c < 128) ? g_ht[(b0 + s) * HH + c] : g_pool[(b0 + s) * 32 + (c - 128)];
    }
    __syncthreads();

    const int g = tid >> 7, j = tid & 127;
    float acc[8];
    float bias = __ldg(fb + j);
#pragma unroll
    for (int ss = 0; ss < 8; ss++) acc[ss] = bias;
    for (int k = 0; k < 160; k++) {
        float w = s_w[j * 161 + k];
#pragma unroll
        for (int ss = 0; ss < 8; ss++)
            acc[ss] = fmaf(w, s_in[(g * 8 + ss) * 160 + k], acc[ss]);
    }
#pragma unroll
    for (int ss = 0; ss < 8; ss++)
        g_fused[(b0 + g * 8 + ss) * HH + j] = fast_tanh(acc[ss]);
}

// ---------------- decoder (2 rows/thread, f32x2) -----------------------------
__global__ __launch_bounds__(256, 2) void dec_kernel(
    const float* __restrict__ w_ih,
    const float* __restrict__ b_ih, const float* __restrict__ b_hh,
    const float* __restrict__ out_w, const float* __restrict__ out_b,
    float* __restrict__ out)
{
    extern __shared__ float sm[];
    float* s_h = sm;                  // 2048
    float* s_c = s_h + NB * HH;       // 2048
    float* s_g = s_c + NB * HH;       // 8192
    float* s_inp = s_g + 4 * NB * HH; // 32
    float* s_ow = s_inp + 32;         // 256

    const int tid = threadIdx.x;
    const int gp = tid >> 7, j = tid & 127;
    const int b0 = blockIdx.x * NB;

    for (int i = tid; i < NB * HH; i += 256) {
        s_h[i] = g_fused[(long)b0 * HH + i];
        s_c[i] = 0.f;
    }
    if (tid < 32) s_inp[tid] = 0.f;
    s_ow[tid] = out_w[tid];
    __syncthreads();

    const int r0 = gp * 256 + j;
    const int r1 = r0 + 128;
    const float bb0 = b_ih[r0] + b_hh[r0];
    const float bb1 = b_ih[r1] + b_hh[r1];
    const float wA0 = w_ih[r0 * 2], wA1 = w_ih[r0 * 2 + 1];
    const float wB0 = w_ih[r1 * 2], wB1 = w_ih[r1 * 2 + 1];
    const float ob = out_b[tid & 1];
    const ulonglong2* wt2 = (const ulonglong2*)g_wtd;

    for (int t = 0; t < PRED; t++) {
        u64 a0[NB], a1[NB];
#pragma unroll
        for (int s = 0; s < NB; s++) {
            float i0 = s_inp[s * 2], i1 = s_inp[s * 2 + 1];
            a0[s] = pk(fmaf(wA1, i1, fmaf(wA0, i0, bb0)), 0.f);
            a1[s] = pk(fmaf(wB1, i1, fmaf(wB0, i0, bb1)), 0.f);
        }
        const ulonglong2* h2 = (const ulonglong2*)s_h;
#pragma unroll 2
        for (int kk = 0; kk < 32; kk++) {
            ulonglong2 w0 = wt2[(kk << 9) + r0];
            ulonglong2 w1 = wt2[(kk << 9) + r1];
#pragma unroll
            for (int s = 0; s < NB; s++) {
                ulonglong2 hv = h2[(s << 5) + kk];
                fma2(a0[s], w0.x, hv.x);
                fma2(a0[s], w0.y, hv.y);
                fma2(a1[s], w1.x, hv.x);
                fma2(a1[s], w1.y, hv.y);
            }
        }
#pragma unroll
        for (int s = 0; s < NB; s++) {
            float v0 = upsum(a0[s]);
            float v1 = upsum(a1[s]);
            v0 = (gp == 1) ? fast_tanh(v0) : fast_sig(v0);
            v1 = fast_sig(v1);
            s_g[((2 * gp) * NB + s) * HH + j] = v0;
            s_g[((2 * gp + 1) * NB + s) * HH + j] = v1;
        }
        __syncthreads();
#pragma unroll
        for (int ss = 0; ss < NB / 2; ss++) {
            int s = gp * (NB / 2) + ss;
            float iv = s_g[(0 * NB + s) * HH + j];
            float fv = s_g[(1 * NB + s) * HH + j];
            float gv = s_g[(2 * NB + s) * HH + j];
            float ov = s_g[(3 * NB + s) * HH + j];
            float c = fmaf(fv, s_c[s * HH + j], iv * gv);
            s_c[s * HH + j] = c;
            s_h[s * HH + j] = ov * fast_tanh(c);
        }
        __syncthreads();
        if (tid < 32) {
            int s = tid >> 1, d = tid & 1;
            const float* hw = s_ow + d * HH;
            const float* hh = s_h + s * HH;
            float psum = ob;
#pragma unroll 8
            for (int k = 0; k < HH; k++) psum = fmaf(hw[k], hh[k], psum);
            out[(long)(b0 + s) * (PRED * 2) + t * 2 + d] = psum;
            s_inp[s * 2 + d] = psum;
        }
        __syncthreads();
    }
}

// ---------------- launch ------------------------------------------------------
extern "C" void kernel_launch(void* const* d_in, const int* in_sizes, int n_in,
                              void* d_out, int out_size)
{
    const float* target  = (const float*)d_in[0];
    const float* neigh   = (const float*)d_in[1];
    const float* enc_w_ih = (const float*)d_in[4];
    const float* enc_w_hh = (const float*)d_in[5];
    const float* enc_b_ih = (const float*)d_in[6];
    const float* enc_b_hh = (const float*)d_in[7];
    const float* nb_w_ih  = (const float*)d_in[8];
    const float* nb_w_hh  = (const float*)d_in[9];
    const float* nb_b_ih  = (const float*)d_in[10];
    const float* nb_b_hh  = (const float*)d_in[11];
    const float* conv1_w  = (const float*)d_in[12];
    const float* conv1_b  = (const float*)d_in[13];
    const float* conv2_w  = (const float*)d_in[14];
    const float* conv2_b  = (const float*)d_in[15];
    const float* fus_w    = (const float*)d_in[16];
    const float* fus_b    = (const float*)d_in[17];
    const float* dec_w_ih = (const float*)d_in[18];
    const float* dec_w_hh = (const float*)d_in[19];
    const float* dec_b_ih = (const float*)d_in[20];
    const float* dec_b_hh = (const float*)d_in[21];
    const float* out_w    = (const float*)d_in[22];
    const float* out_b    = (const float*)d_in[23];
    float* out = (float*)d_out;

    const int ENC_SMEM  = (NB * TT * FF + 2 * NB * HH + 4 * NB * HH + 4 * HH * FF + 512) * 4;
    const int C1_SMEM   = (8 * 9 * 132 + 32 * 9 * 132) * 4;
    const int C2_SMEM   = (8192 + 32 * 577) * 4;
    const int FUSE_SMEM = (128 * 161 + 32 * 160) * 4;
    const int DEC_SMEM  = (2 * NB * HH + 4 * NB * HH + 32 + 256) * 4;

    cudaFuncSetAttribute(enc_kernel,  cudaFuncAttributeMaxDynamicSharedMemorySize, ENC_SMEM);
    cudaFuncSetAttribute(conv1_kernel, cudaFuncAttributeMaxDynamicSharedMemorySize, C1_SMEM);
    cudaFuncSetAttribute(conv2_kernel, cudaFuncAttributeMaxDynamicSharedMemorySize, C2_SMEM);
    cudaFuncSetAttribute(fuse_kernel, cudaFuncAttributeMaxDynamicSharedMemorySize, FUSE_SMEM);
    cudaFuncSetAttribute(dec_kernel,  cudaFuncAttributeMaxDynamicSharedMemorySize, DEC_SMEM);

    float* d_wte; cudaGetSymbolAddress((void**)&d_wte, g_wte);
    float* d_wtn; cudaGetSymbolAddress((void**)&d_wtn, g_wtn);
    float* d_wtd; cudaGetSymbolAddress((void**)&d_wtd, g_wtd);

    transpose_kernel<<<256, 256>>>(enc_w_hh, d_wte);
    transpose_kernel<<<256, 256>>>(nb_w_hh,  d_wtn);
    transpose_kernel<<<256, 256>>>(dec_w_hh, d_wtd);

    // merged encoders: 512 target blocks + 4096 neighbor blocks
    enc_kernel<<<TBLK + BATCH * KN / NB, 256, ENC_SMEM>>>(
        target, neigh, enc_w_ih, nb_w_ih,
        enc_b_ih, enc_b_hh, nb_b_ih, nb_b_hh);

    conv1_kernel<<<BATCH / 8, 256, C1_SMEM>>>(conv1_w, conv1_b);
    conv2_kernel<<<BATCH / 2, 256, C2_SMEM>>>(conv2_w, conv2_b);
    fuse_kernel<<<BATCH / 32, 512, FUSE_SMEM>>>(fus_w, fus_b);
    dec_kernel<<<BATCH / NB, 256, DEC_SMEM>>>(dec_w_ih, dec_b_ih, dec_b_hh,
                                              out_w, out_b, out);
}

// round 5
// speedup vs baseline: 2.7081x; 1.3427x over previous
#include <cuda_runtime.h>
#include <math.h>

#define BATCH 8192
#define KN 8
#define TT 20
#define FF 7
#define HH 128
#define NB 16          // sequences per LSTM block
#define PRED 25
#define TBLK (BATCH/NB)   // 512 target-encoder blocks
#define HP 20          // padded [k][s] row stride (floats) for conflict-free STS

typedef unsigned long long u64;

// ---------------- f32x2 helpers ----------------------------------------------
__device__ __forceinline__ void fma2(u64 &a, u64 x, u64 y){
    asm("fma.rn.f32x2 %0, %1, %2, %0;" : "+l"(a) : "l"(x), "l"(y));
}
__device__ __forceinline__ u64 pk(float lo, float hi){
    u64 r; asm("mov.b64 %0, {%1,%2};" : "=l"(r) : "f"(lo), "f"(hi)); return r;
}
__device__ __forceinline__ float upsum(u64 a){
    float lo, hi; asm("mov.b64 {%0,%1}, %2;" : "=f"(lo), "=f"(hi) : "l"(a));
    return lo + hi;
}
__device__ __forceinline__ float2 up2(u64 a){
    float lo, hi; asm("mov.b64 {%0,%1}, %2;" : "=f"(lo), "=f"(hi) : "l"(a));
    return make_float2(lo, hi);
}
__device__ __forceinline__ float fast_sig(float v){
    return __fdividef(1.f, 1.f + __expf(-v));
}
__device__ __forceinline__ float fast_tanh(float v){
    return 1.f - __fdividef(2.f, 1.f + __expf(2.f * v));
}

// ---------------- scratch ------------------------------------------------------
__device__ float g_ht[BATCH * HH];
__device__ float g_hn[BATCH * KN * HH];
__device__ float g_y1[BATCH * 64 * 64];
__device__ float g_pool[BATCH * 32];
__device__ float g_fused[BATCH * HH];
__device__ float g_wte[4 * HH * HH];   // transposed enc w_hh: [kk][row][4]
__device__ float g_wtn[4 * HH * HH];
__device__ float g_wtd[4 * HH * HH];

// ---------------- w_hh transpose: [row][k] -> [kk][row][4] --------------------
__global__ void transpose_kernel(const float* __restrict__ w, float* __restrict__ wt){
    int i = blockIdx.x * 256 + threadIdx.x;
    int row = i >> 7, k = i & 127;
    int kk = k >> 2, r = k & 3;
    wt[(((kk << 9) + row) << 2) + r] = w[i];
}

// ---------------- merged encoder: 4 rows/thread, seq-pair packed acc ----------
__global__ __launch_bounds__(128, 3) void enc_kernel(
    const float* __restrict__ tgt_x, const float* __restrict__ nb_x,
    const float* __restrict__ e_wih, const float* __restrict__ n_wih,
    const float* __restrict__ e_bi,  const float* __restrict__ e_bh,
    const float* __restrict__ n_bi,  const float* __restrict__ n_bh)
{
    extern __shared__ float sm[];
    float* s_x   = sm;                       // NB*TT*FF = 2240
    float* s_h   = s_x + NB * TT * FF;       // 2 * 128 * HP = 5120
    float* s_wih = s_h + 2 * HH * HP;        // 3584
    float* s_b   = s_wih + 4 * HH * FF;      // 512

    const int j = threadIdx.x;               // hidden unit 0..127

    const bool is_tgt = (blockIdx.x < TBLK);
    const int seq0 = (is_tgt ? blockIdx.x : (blockIdx.x - TBLK)) * NB;
    const float* x    = is_tgt ? tgt_x : nb_x;
    const float* wih  = is_tgt ? e_wih : n_wih;
    const float* bi   = is_tgt ? e_bi  : n_bi;
    const float* bh   = is_tgt ? e_bh  : n_bh;
    const float* wt   = is_tgt ? g_wte : g_wtn;
    float* h_out      = is_tgt ? g_ht  : g_hn;

    for (int i = j; i < 4 * HH * FF; i += 128) s_wih[i] = wih[i];
    for (int i = j; i < 512; i += 128) s_b[i] = bi[i] + bh[i];
    for (int i = j; i < NB * TT * FF; i += 128) s_x[i] = x[(long)seq0 * (TT * FF) + i];
    for (int i = j; i < HH * HP; i += 128) s_h[i] = 0.f;
    __syncthreads();

    // per-thread constants: rows {j, 128+j, 256+j, 384+j} = gates i,f,g,o of unit j
    float bbv[4], wi[4][FF];
#pragma unroll
    for (int r = 0; r < 4; r++) {
        bbv[r] = s_b[r * HH + j];
#pragma unroll
        for (int f = 0; f < FF; f++) wi[r][f] = s_wih[(r * HH + j) * FF + f];
    }
    u64 c2[8];
#pragma unroll
    for (int sp = 0; sp < 8; sp++) c2[sp] = 0ull;

    const float4* wt4 = (const float4*)wt;   // idx = (kk<<9) + row
    int cur = 0;
    u64 hu[8];

    for (int t = 0; t < TT; t++) {
        const float* hc = s_h + cur * HH * HP;
        float* hn = s_h + (cur ^ 1) * HH * HP;

        u64 acc[4][8];
#pragma unroll
        for (int sp = 0; sp < 8; sp++) {
            const float* xa = s_x + ((2 * sp) * TT + t) * FF;
            const float* xb = xa + TT * FF;
            float A[4], B[4];
#pragma unroll
            for (int r = 0; r < 4; r++) { A[r] = bbv[r]; B[r] = bbv[r]; }
#pragma unroll
            for (int f = 0; f < FF; f++) {
                float va = xa[f], vb = xb[f];
#pragma unroll
                for (int r = 0; r < 4; r++) {
                    A[r] = fmaf(wi[r][f], va, A[r]);
                    B[r] = fmaf(wi[r][f], vb, B[r]);
                }
            }
#pragma unroll
            for (int r = 0; r < 4; r++) acc[r][sp] = pk(A[r], B[r]);
        }

        const ulonglong2* h2 = (const ulonglong2*)hc;   // [k]: 5 u2 per row (HP=20)
#define KSTEP(CMP, KOFF) { \
            const ulonglong2* hb = h2 + ((kk << 2) + (KOFF)) * (HP / 4); \
            ulonglong2 hA = hb[0], hB = hb[1], hC = hb[2], hD = hb[3]; \
            u64 hp[8] = {hA.x, hA.y, hB.x, hB.y, hC.x, hC.y, hD.x, hD.y}; \
            u64 W0 = pk(qa.CMP, qa.CMP), W1 = pk(qb.CMP, qb.CMP); \
            u64 W2 = pk(qc.CMP, qc.CMP), W3 = pk(qd.CMP, qd.CMP); \
            _Pragma("unroll") \
            for (int sp = 0; sp < 8; sp++) { \
                fma2(acc[0][sp], W0, hp[sp]); \
                fma2(acc[1][sp], W1, hp[sp]); \
                fma2(acc[2][sp], W2, hp[sp]); \
                fma2(acc[3][sp], W3, hp[sp]); \
            } }

        for (int kk = 0; kk < 32; kk++) {
            float4 qa = wt4[(kk << 9) + j];
            float4 qb = wt4[(kk << 9) + j + 128];
            float4 qc = wt4[(kk << 9) + j + 256];
            float4 qd = wt4[(kk << 9) + j + 384];
            KSTEP(x, 0) KSTEP(y, 1) KSTEP(z, 2) KSTEP(w, 3)
        }
#undef KSTEP

#pragma unroll
        for (int sp = 0; sp < 8; sp++) {
            float2 xi = up2(acc[0][sp]);
            float2 xf = up2(acc[1][sp]);
            float2 xg = up2(acc[2][sp]);
            float2 xo = up2(acc[3][sp]);
            float i0 = fast_sig(xi.x), i1 = fast_sig(xi.y);
            float f0 = fast_sig(xf.x), f1 = fast_sig(xf.y);
            float g0 = fast_tanh(xg.x), g1 = fast_tanh(xg.y);
            float o0 = fast_sig(xo.x), o1 = fast_sig(xo.y);
            float2 cc = up2(c2[sp]);
            float cn0 = fmaf(f0, cc.x, i0 * g0);
            float cn1 = fmaf(f1, cc.y, i1 * g1);
            c2[sp] = pk(cn0, cn1);
            hu[sp] = pk(o0 * fast_tanh(cn0), o1 * fast_tanh(cn1));
        }
        ulonglong2* hw = (ulonglong2*)(hn + j * HP);
        hw[0] = make_ulonglong2(hu[0], hu[1]);
        hw[1] = make_ulonglong2(hu[2], hu[3]);
        hw[2] = make_ulonglong2(hu[4], hu[5]);
        hw[3] = make_ulonglong2(hu[6], hu[7]);
        __syncthreads();
        cur ^= 1;
    }

    // coalesced output: h_out[(seq0+s)*128 + k] from s_h[cur][k][s]
    const float* hf = s_h + cur * HH * HP;
    for (int i = j; i < NB * HH; i += 128) {
        int s = i >> 7, k = i & 127;
        h_out[(long)(seq0 + s) * HH + k] = hf[k * HP + s];
    }
}

// ---------------- conv1: sparse social grid, weights staged in smem -----------
__global__ __launch_bounds__(256) void conv1_kernel(
    const float* __restrict__ w1, const float* __restrict__ b1)
{
    extern __shared__ float sm[];
    float* s_v = sm;                 // 8*9*132
    float* s_w = sm + 8 * 9 * 132;   // 32*9*132
    const int tid = threadIdx.x;
    const int b0 = blockIdx.x * 8;

    for (int i = tid; i < 8 * 9 * 128; i += 256) {
        int b = i / 1152, r = i % 1152, cell = r >> 7, c = r & 127;
        float v = (cell == 0) ? g_ht[(b0 + b) * HH + c]
                              : g_hn[((b0 + b) * KN + cell - 1) * HH + c];
        s_v[(b * 9 + cell) * 132 + c] = v;
    }

    const int o = tid >> 3, b = tid & 7;
    const float* vb = s_v + b * 1188;

    for (int half = 0; half < 2; half++) {
        __syncthreads();
        for (int i = tid; i < 32 * 1152; i += 256) {
            int oo = i / 1152, r = i % 1152, c = r / 9, tap = r % 9;
            s_w[oo * 1188 + tap * 132 + c] = w1[half * 32 * 1152 + i];
        }
        __syncthreads();

        const int och = half * 32 + o;
        const float bias = __ldg(b1 + och);
        const float* wb = s_w + o * 1188;
        const int CY[9] = {4, 0, 0, 0, 0, 0, 0, 0, 1};
        const int CX[9] = {4, 1, 2, 3, 4, 5, 6, 7, 0};

        for (int p = 0; p < 8; p++) {
            u64 acc[8];
#pragma unroll
            for (int q = 0; q < 8; q++) acc[q] = pk(bias, 0.f);
#pragma unroll
            for (int ci = 0; ci < 9; ci++) {
                const int cx = CX[ci];
                int dy = CY[ci] - p;
                if (dy < -1 || dy > 1) continue;
                const ulonglong2* vp  = (const ulonglong2*)(vb + ci * 132);
                const ulonglong2* wL  = (const ulonglong2*)(wb + ((dy + 1) * 3 + 2) * 132);
                const ulonglong2* wC  = (const ulonglong2*)(wb + ((dy + 1) * 3 + 1) * 132);
                const ulonglong2* wR  = (const ulonglong2*)(wb + ((dy + 1) * 3 + 0) * 132);
#pragma unroll 8
                for (int cc = 0; cc < 32; cc++) {
                    ulonglong2 vv = vp[cc];
                    if (cx - 1 >= 0) {
                        ulonglong2 wv = wL[cc];
                        fma2(acc[cx - 1], wv.x, vv.x);
                        fma2(acc[cx - 1], wv.y, vv.y);
                    }
                    {
                        ulonglong2 wv = wC[cc];
                        fma2(acc[cx], wv.x, vv.x);
                        fma2(acc[cx], wv.y, vv.y);
                    }
                    if (cx + 1 <= 7) {
                        ulonglong2 wv = wR[cc];
                        fma2(acc[cx + 1], wv.x, vv.x);
                        fma2(acc[cx + 1], wv.y, vv.y);
                    }
                }
            }
            float oq[8];
#pragma unroll
            for (int q = 0; q < 8; q++) oq[q] = fmaxf(upsum(acc[q]), 0.f);
            float4* dst = (float4*)(g_y1 + ((long)(b0 + b) * 64 + och) * 64 + p * 8);
            dst[0] = make_float4(oq[0], oq[1], oq[2], oq[3]);
            dst[1] = make_float4(oq[4], oq[5], oq[6], oq[7]);
        }
    }
}

// ---------------- conv2 + relu + maxpool ---------------------------------------
__global__ __launch_bounds__(256) void conv2_kernel(
    const float* __restrict__ w2, const float* __restrict__ b2)
{
    extern __shared__ float sm[];
    float* s_y = sm;                 // 8192
    float* s_w = sm + 8192;          // 32*577
    const int tid = threadIdx.x;
    const int b0 = blockIdx.x * 2;

    for (int i = tid; i < 8192; i += 256) s_y[i] = g_y1[(long)b0 * 4096 + i];
    for (int i = tid; i < 32 * 576; i += 256) {
        int c2 = i / 576, r = i % 576;
        s_w[c2 * 577 + r] = w2[i];
    }
    __syncthreads();

    const int b  = tid >> 7;
    const int cp = (tid >> 3) & 15;
    const int p  = tid & 7;
    const int c2a = cp, c2b = cp + 16;

    u64 acca[4], accb[4];
#pragma unroll
    for (int m = 0; m < 4; m++) { acca[m] = 0ull; accb[m] = 0ull; }

    for (int ty = 0; ty < 3; ty++) {
        int ip = p + ty - 1;
        if (ip < 0 || ip > 7) continue;
        for (int c1 = 0; c1 < 64; c1++) {
            const float4* yr = (const float4*)(s_y + ((b * 64 + c1) * 64 + ip * 8));
            float4 a0 = yr[0], a1 = yr[1];
            u64 C0 = pk(a0.x, a0.y), C1 = pk(a0.z, a0.w);
            u64 C2 = pk(a1.x, a1.y), C3 = pk(a1.z, a1.w);
            u64 L0 = pk(0.f,  a0.x), L1 = pk(a0.y, a0.z);
            u64 L2 = pk(a0.w, a1.x), L3 = pk(a1.y, a1.z);
            u64 R3 = pk(a1.w, 0.f);
            const float* wpa = s_w + c2a * 577 + c1 * 9 + ty * 3;
            const float* wpb = s_w + c2b * 577 + c1 * 9 + ty * 3;
            u64 W0a = pk(wpa[0], wpa[0]), W1a = pk(wpa[1], wpa[1]), W2a = pk(wpa[2], wpa[2]);
            u64 W0b = pk(wpb[0], wpb[0]), W1b = pk(wpb[1], wpb[1]), W2b = pk(wpb[2], wpb[2]);
            fma2(acca[0], W1a, C0); fma2(acca[1], W1a, C1);
            fma2(acca[2], W1a, C2); fma2(acca[3], W1a, C3);
            fma2(acca[0], W0a, L0); fma2(acca[1], W0a, L1);
            fma2(acca[2], W0a, L2); fma2(acca[3], W0a, L3);
            fma2(acca[0], W2a, L1); fma2(acca[1], W2a, L2);
            fma2(acca[2], W2a, L3); fma2(acca[3], W2a, R3);
            fma2(accb[0], W1b, C0); fma2(accb[1], W1b, C1);
            fma2(accb[2], W1b, C2); fma2(accb[3], W1b, C3);
            fma2(accb[0], W0b, L0); fma2(accb[1], W0b, L1);
            fma2(accb[2], W0b, L2); fma2(accb[3], W0b, L3);
            fma2(accb[0], W2b, L1); fma2(accb[1], W2b, L2);
            fma2(accb[2], W2b, L3); fma2(accb[3], W2b, R3);
        }
    }
    float bia = __ldg(b2 + c2a), bib = __ldg(b2 + c2b);
    float ma = 0.f, mb = 0.f;
#pragma unroll
    for (int m = 0; m < 4; m++) {
        float2 fa = up2(acca[m]);
        float2 fb = up2(accb[m]);
        ma = fmaxf(ma, fmaxf(fa.x, fa.y) + bia);
        mb = fmaxf(mb, fmaxf(fb.x, fb.y) + bib);
    }
    for (int off = 4; off; off >>= 1) {
        ma = fmaxf(ma, __shfl_xor_sync(0xffffffffu, ma, off));
        mb = fmaxf(mb, __shfl_xor_sync(0xffffffffu, mb, off));
    }
    if (p == 0) {
        g_pool[(b0 + b) * 32 + c2a] = ma;
        g_pool[(b0 + b) * 32 + c2b] = mb;
    }
}

// ---------------- fusion --------------------------------------------------------
__global__ __launch_bounds__(512) void fuse_kernel(
    const float* __restrict__ fw, const float* __restrict__ fb)
{
    extern __shared__ float sm[];
    float* s_w = sm;                 // 128*161
    float* s_in = sm + 128 * 161;    // 32*160
    const int tid = threadIdx.x;
    const int b0 = blockIdx.x * 32;

    for (int i = tid; i < 128 * 160; i += 512) {
        int r = i / 160, c = i % 160;
        s_w[r * 161 + c] = fw[i];
    }
    for (int i = tid; i < 32 * 160; i += 512) {
        int s = i / 160, c = i % 160;
        s_in[i] = (c < 128) ? g_ht[(b0 + s) * HH + c] : g_pool[(b0 + s) * 32 + (c - 128)];
    }
    __syncthreads();

    const int g = tid >> 7, j = tid & 127;
    float acc[8];
    float bias = __ldg(fb + j);
#pragma unroll
    for (int ss = 0; ss < 8; ss++) acc[ss] = bias;
    for (int k = 0; k < 160; k++) {
        float w = s_w[j * 161 + k];
#pragma unroll
        for (int ss = 0; ss < 8; ss++)
            acc[ss] = fmaf(w, s_in[(g * 8 + ss) * 160 + k], acc[ss]);
    }
#pragma unroll
    for (int ss = 0; ss < 8; ss++)
        g_fused[(b0 + g * 8 + ss) * HH + j] = fast_tanh(acc[ss]);
}

// ---------------- decoder: 4 rows/thread, seq-pair packed ----------------------
__global__ __launch_bounds__(128, 3) void dec_kernel(
    const float* __restrict__ w_ih,
    const float* __restrict__ b_ih, const float* __restrict__ b_hh,
    const float* __restrict__ out_w, const float* __restrict__ out_b,
    float* __restrict__ out)
{
    extern __shared__ float sm[];
    float* s_h   = sm;                 // 2*128*HP = 5120
    float* s_inp = s_h + 2 * HH * HP;  // 32
    float* s_ow  = s_inp + 32;         // 256

    const int j = threadIdx.x;
    const int b0 = blockIdx.x * NB;

    // init h buffer 0 from g_fused (coalesced read, strided smem write)
    for (int i = j; i < NB * HH; i += 128) {
        int s = i >> 7, k = i & 127;
        s_h[k * HP + s] = g_fused[(long)b0 * HH + i];
    }
    if (j < 32) s_inp[j] = 0.f;
    for (int i = j; i < 256; i += 128) s_ow[i] = out_w[i];
    __syncthreads();

    float bbv[4], wiA[4], wiB[4];
#pragma unroll
    for (int r = 0; r < 4; r++) {
        int row = r * HH + j;
        bbv[r] = b_ih[row] + b_hh[row];
        wiA[r] = w_ih[row * 2];
        wiB[r] = w_ih[row * 2 + 1];
    }
    const float ob = out_b[j & 1];
    u64 c2[8];
#pragma unroll
    for (int sp = 0; sp < 8; sp++) c2[sp] = 0ull;

    const float4* wt4 = (const float4*)g_wtd;
    int cur = 0;
    u64 hu[8];

    for (int t = 0; t < PRED; t++) {
        const float* hc = s_h + cur * HH * HP;
        float* hn = s_h + (cur ^ 1) * HH * HP;

        u64 acc[4][8];
#pragma unroll
        for (int sp = 0; sp < 8; sp++) {
            float a0 = s_inp[4 * sp + 0], a1 = s_inp[4 * sp + 1];
            float b0v = s_inp[4 * sp + 2], b1v = s_inp[4 * sp + 3];
#pragma unroll
            for (int r = 0; r < 4; r++) {
                float A = fmaf(wiB[r], a1, fmaf(wiA[r], a0, bbv[r]));
                float B = fmaf(wiB[r], b1v, fmaf(wiA[r], b0v, bbv[r]));
                acc[r][sp] = pk(A, B);
            }
        }

        const ulonglong2* h2 = (const ulonglong2*)hc;
#define KSTEP(CMP, KOFF) { \
            const ulonglong2* hb = h2 + ((kk << 2) + (KOFF)) * (HP / 4); \
            ulonglong2 hA = hb[0], hB = hb[1], hC = hb[2], hD = hb[3]; \
            u64 hp[8] = {hA.x, hA.y, hB.x, hB.y, hC.x, hC.y, hD.x, hD.y}; \
            u64 W0 = pk(qa.CMP, qa.CMP), W1 = pk(qb.CMP, qb.CMP); \
            u64 W2 = pk(qc.CMP, qc.CMP), W3 = pk(qd.CMP, qd.CMP); \
            _Pragma("unroll") \
            for (int sp = 0; sp < 8; sp++) { \
                fma2(acc[0][sp], W0, hp[sp]); \
                fma2(acc[1][sp], W1, hp[sp]); \
                fma2(acc[2][sp], W2, hp[sp]); \
                fma2(acc[3][sp], W3, hp[sp]); \
            } }

        for (int kk = 0; kk < 32; kk++) {
            float4 qa = wt4[(kk << 9) + j];
            float4 qb = wt4[(kk << 9) + j + 128];
            float4 qc = wt4[(kk << 9) + j + 256];
            float4 qd = wt4[(kk << 9) + j + 384];
            KSTEP(x, 0) KSTEP(y, 1) KSTEP(z, 2) KSTEP(w, 3)
        }
#undef KSTEP

#pragma unroll
        for (int sp = 0; sp < 8; sp++) {
            float2 xi = up2(acc[0][sp]);
            float2 xf = up2(acc[1][sp]);
            float2 xg = up2(acc[2][sp]);
            float2 xo = up2(acc[3][sp]);
            float i0 = fast_sig(xi.x), i1 = fast_sig(xi.y);
            float f0 = fast_sig(xf.x), f1 = fast_sig(xf.y);
            float g0 = fast_tanh(xg.x), g1 = fast_tanh(xg.y);
            float o0 = fast_sig(xo.x), o1 = fast_sig(xo.y);
            float2 cc = up2(c2[sp]);
            float cn0 = fmaf(f0, cc.x, i0 * g0);
            float cn1 = fmaf(f1, cc.y, i1 * g1);
            c2[sp] = pk(cn0, cn1);
            hu[sp] = pk(o0 * fast_tanh(cn0), o1 * fast_tanh(cn1));
        }
        ulonglong2* hw = (ulonglong2*)(hn + j * HP);
        hw[0] = make_ulonglong2(hu[0], hu[1]);
        hw[1] = make_ulonglong2(hu[2], hu[3]);
        hw[2] = make_ulonglong2(hu[4], hu[5]);
        hw[3] = make_ulonglong2(hu[6], hu[7]);
        __syncthreads();
        cur ^= 1;

        // output projection from hn = s_h[cur]
        if (j < 32) {
            int s = j >> 1, d = j & 1;
            const float* hw2 = s_ow + d * HH;
            const float* hh = s_h + cur * HH * HP;
            float psum = ob;
#pragma unroll 8
            for (int k = 0; k < HH; k++) psum = fmaf(hw2[k], hh[k * HP + s], psum);
            out[(long)(b0 + s) * (PRED * 2) + t * 2 + d] = psum;
            s_inp[s * 2 + d] = psum;
        }
        __syncthreads();
    }
}

// ---------------- launch ---------------------------------------------------------
extern "C" void kernel_launch(void* const* d_in, const int* in_sizes, int n_in,
                              void* d_out, int out_size)
{
    const float* target  = (const float*)d_in[0];
    const float* neigh   = (const float*)d_in[1];
    const float* enc_w_ih = (const float*)d_in[4];
    const float* enc_w_hh = (const float*)d_in[5];
    const float* enc_b_ih = (const float*)d_in[6];
    const float* enc_b_hh = (const float*)d_in[7];
    const float* nb_w_ih  = (const float*)d_in[8];
    const float* nb_w_hh  = (const float*)d_in[9];
    const float* nb_b_ih  = (const float*)d_in[10];
    const float* nb_b_hh  = (const float*)d_in[11];
    const float* conv1_w  = (const float*)d_in[12];
    const float* conv1_b  = (const float*)d_in[13];
    const float* conv2_w  = (const float*)d_in[14];
    const float* conv2_b  = (const float*)d_in[15];
    const float* fus_w    = (const float*)d_in[16];
    const float* fus_b    = (const float*)d_in[17];
    const float* dec_w_ih = (const float*)d_in[18];
    const float* dec_w_hh = (const float*)d_in[19];
    const float* dec_b_ih = (const float*)d_in[20];
    const float* dec_b_hh = (const float*)d_in[21];
    const float* out_w    = (const float*)d_in[22];
    const float* out_b    = (const float*)d_in[23];
    float* out = (float*)d_out;

    const int ENC_SMEM  = (NB * TT * FF + 2 * HH * HP + 4 * HH * FF + 512) * 4;
    const int C1_SMEM   = (8 * 9 * 132 + 32 * 9 * 132) * 4;
    const int C2_SMEM   = (8192 + 32 * 577) * 4;
    const int FUSE_SMEM = (128 * 161 + 32 * 160) * 4;
    const int DEC_SMEM  = (2 * HH * HP + 32 + 256) * 4;

    cudaFuncSetAttribute(enc_kernel,  cudaFuncAttributeMaxDynamicSharedMemorySize, ENC_SMEM);
    cudaFuncSetAttribute(conv1_kernel, cudaFuncAttributeMaxDynamicSharedMemorySize, C1_SMEM);
    cudaFuncSetAttribute(conv2_kernel, cudaFuncAttributeMaxDynamicSharedMemorySize, C2_SMEM);
    cudaFuncSetAttribute(fuse_kernel, cudaFuncAttributeMaxDynamicSharedMemorySize, FUSE_SMEM);
    cudaFuncSetAttribute(dec_kernel,  cudaFuncAttributeMaxDynamicSharedMemorySize, DEC_SMEM);

    float* d_wte; cudaGetSymbolAddress((void**)&d_wte, g_wte);
    float* d_wtn; cudaGetSymbolAddress((void**)&d_wtn, g_wtn);
    float* d_wtd; cudaGetSymbolAddress((void**)&d_wtd, g_wtd);

    transpose_kernel<<<256, 256>>>(enc_w_hh, d_wte);
    transpose_kernel<<<256, 256>>>(nb_w_hh,  d_wtn);
    transpose_kernel<<<256, 256>>>(dec_w_hh, d_wtd);

    enc_kernel<<<TBLK + BATCH * KN / NB, 128, ENC_SMEM>>>(
        target, neigh, enc_w_ih, nb_w_ih,
        enc_b_ih, enc_b_hh, nb_b_ih, nb_b_hh);

    conv1_kernel<<<BATCH / 8, 256, C1_SMEM>>>(conv1_w, conv1_b);
    conv2_kernel<<<BATCH / 2, 256, C2_SMEM>>>(conv2_w, conv2_b);
    fuse_kernel<<<BATCH / 32, 512, FUSE_SMEM>>>(fus_w, fus_b);
    dec_kernel<<<BATCH / NB, 128, DEC_SMEM>>>(dec_w_ih, dec_b_ih, dec_b_hh,
                                              out_w, out_b, out);
}

// round 6
// speedup vs baseline: 2.7976x; 1.0330x over previous
#include <cuda_runtime.h>
#include <math.h>

#define BATCH 8192
#define KN 8
#define TT 20
#define FF 7
#define HH 128
#define NB 8           // sequences per LSTM block (v6: 4 blocks/SM)
#define SP (NB/2)      // seq pairs per thread
#define PRED 25
#define TBLK (BATCH/NB)   // 1024 target-encoder blocks
#define HP 12          // padded [k][s] row stride (floats): 8 data + 4 pad

typedef unsigned long long u64;

// ---------------- f32x2 helpers ----------------------------------------------
__device__ __forceinline__ void fma2(u64 &a, u64 x, u64 y){
    asm("fma.rn.f32x2 %0, %1, %2, %0;" : "+l"(a) : "l"(x), "l"(y));
}
__device__ __forceinline__ u64 pk(float lo, float hi){
    u64 r; asm("mov.b64 %0, {%1,%2};" : "=l"(r) : "f"(lo), "f"(hi)); return r;
}
__device__ __forceinline__ float upsum(u64 a){
    float lo, hi; asm("mov.b64 {%0,%1}, %2;" : "=f"(lo), "=f"(hi) : "l"(a));
    return lo + hi;
}
__device__ __forceinline__ float2 up2(u64 a){
    float lo, hi; asm("mov.b64 {%0,%1}, %2;" : "=f"(lo), "=f"(hi) : "l"(a));
    return make_float2(lo, hi);
}
__device__ __forceinline__ float fast_sig(float v){
    return __fdividef(1.f, 1.f + __expf(-v));
}
__device__ __forceinline__ float fast_tanh(float v){
    return 1.f - __fdividef(2.f, 1.f + __expf(2.f * v));
}

// ---------------- scratch ------------------------------------------------------
__device__ float g_ht[BATCH * HH];
__device__ float g_hn[BATCH * KN * HH];
__device__ float g_y1[BATCH * 64 * 64];
__device__ float g_pool[BATCH * 32];
__device__ float g_fused[BATCH * HH];
__device__ float g_wte[4 * HH * HH];   // transposed enc w_hh: [kk][row][4]
__device__ float g_wtn[4 * HH * HH];
__device__ float g_wtd[4 * HH * HH];

// ---------------- w_hh transpose: [row][k] -> [kk][row][4] --------------------
__global__ void transpose_kernel(const float* __restrict__ w, float* __restrict__ wt){
    int i = blockIdx.x * 256 + threadIdx.x;
    int row = i >> 7, k = i & 127;
    int kk = k >> 2, r = k & 3;
    wt[(((kk << 9) + row) << 2) + r] = w[i];
}

// ---------------- merged encoder: 4 rows/thread, NB=8, 4 blocks/SM -------------
__global__ __launch_bounds__(128, 4) void enc_kernel(
    const float* __restrict__ tgt_x, const float* __restrict__ nb_x,
    const float* __restrict__ e_wih, const float* __restrict__ n_wih,
    const float* __restrict__ e_bi,  const float* __restrict__ e_bh,
    const float* __restrict__ n_bi,  const float* __restrict__ n_bh)
{
    extern __shared__ float sm[];
    float* s_x   = sm;                       // NB*TT*FF = 1120
    float* s_h   = s_x + NB * TT * FF;       // 2 * 128 * HP = 3072
    float* s_wih = s_h + 2 * HH * HP;        // 3584
    float* s_b   = s_wih + 4 * HH * FF;      // 512

    const int j = threadIdx.x;               // hidden unit 0..127

    const bool is_tgt = (blockIdx.x < TBLK);
    const int seq0 = (is_tgt ? blockIdx.x : (blockIdx.x - TBLK)) * NB;
    const float* x    = is_tgt ? tgt_x : nb_x;
    const float* wih  = is_tgt ? e_wih : n_wih;
    const float* bi   = is_tgt ? e_bi  : n_bi;
    const float* bh   = is_tgt ? e_bh  : n_bh;
    const float* wt   = is_tgt ? g_wte : g_wtn;
    float* h_out      = is_tgt ? g_ht  : g_hn;

    for (int i = j; i < 4 * HH * FF; i += 128) s_wih[i] = wih[i];
    for (int i = j; i < 512; i += 128) s_b[i] = bi[i] + bh[i];
    for (int i = j; i < NB * TT * FF; i += 128) s_x[i] = x[(long)seq0 * (TT * FF) + i];
    for (int i = j; i < HH * HP; i += 128) s_h[i] = 0.f;
    __syncthreads();

    float bbv[4], wi[4][FF];
#pragma unroll
    for (int r = 0; r < 4; r++) {
        bbv[r] = s_b[r * HH + j];
#pragma unroll
        for (int f = 0; f < FF; f++) wi[r][f] = s_wih[(r * HH + j) * FF + f];
    }
    u64 c2[SP];
#pragma unroll
    for (int sp = 0; sp < SP; sp++) c2[sp] = 0ull;

    const float4* wt4 = (const float4*)wt;
    int cur = 0;
    u64 hu[SP];

    for (int t = 0; t < TT; t++) {
        const float* hc = s_h + cur * HH * HP;
        float* hn = s_h + (cur ^ 1) * HH * HP;

        u64 acc[4][SP];
#pragma unroll
        for (int sp = 0; sp < SP; sp++) {
            const float* xa = s_x + ((2 * sp) * TT + t) * FF;
            const float* xb = xa + TT * FF;
            float A[4], B[4];
#pragma unroll
            for (int r = 0; r < 4; r++) { A[r] = bbv[r]; B[r] = bbv[r]; }
#pragma unroll
            for (int f = 0; f < FF; f++) {
                float va = xa[f], vb = xb[f];
#pragma unroll
                for (int r = 0; r < 4; r++) {
                    A[r] = fmaf(wi[r][f], va, A[r]);
                    B[r] = fmaf(wi[r][f], vb, B[r]);
                }
            }
#pragma unroll
            for (int r = 0; r < 4; r++) acc[r][sp] = pk(A[r], B[r]);
        }

        const ulonglong2* h2 = (const ulonglong2*)hc;   // HP/4=3 u2 per k-row
#define KSTEP(CMP, KOFF) { \
            const ulonglong2* hb = h2 + ((kk << 2) + (KOFF)) * (HP / 4); \
            ulonglong2 hA = hb[0], hB = hb[1]; \
            u64 hp[SP] = {hA.x, hA.y, hB.x, hB.y}; \
            u64 W0 = pk(qa.CMP, qa.CMP), W1 = pk(qb.CMP, qb.CMP); \
            u64 W2 = pk(qc.CMP, qc.CMP), W3 = pk(qd.CMP, qd.CMP); \
            _Pragma("unroll") \
            for (int sp = 0; sp < SP; sp++) { \
                fma2(acc[0][sp], W0, hp[sp]); \
                fma2(acc[1][sp], W1, hp[sp]); \
                fma2(acc[2][sp], W2, hp[sp]); \
                fma2(acc[3][sp], W3, hp[sp]); \
            } }

        for (int kk = 0; kk < 32; kk++) {
            float4 qa = wt4[(kk << 9) + j];
            float4 qb = wt4[(kk << 9) + j + 128];
            float4 qc = wt4[(kk << 9) + j + 256];
            float4 qd = wt4[(kk << 9) + j + 384];
            KSTEP(x, 0) KSTEP(y, 1) KSTEP(z, 2) KSTEP(w, 3)
        }
#undef KSTEP

#pragma unroll
        for (int sp = 0; sp < SP; sp++) {
            float2 xi = up2(acc[0][sp]);
            float2 xf = up2(acc[1][sp]);
            float2 xg = up2(acc[2][sp]);
            float2 xo = up2(acc[3][sp]);
            float i0 = fast_sig(xi.x), i1 = fast_sig(xi.y);
            float f0 = fast_sig(xf.x), f1 = fast_sig(xf.y);
            float g0 = fast_tanh(xg.x), g1 = fast_tanh(xg.y);
            float o0 = fast_sig(xo.x), o1 = fast_sig(xo.y);
            float2 cc = up2(c2[sp]);
            float cn0 = fmaf(f0, cc.x, i0 * g0);
            float cn1 = fmaf(f1, cc.y, i1 * g1);
            c2[sp] = pk(cn0, cn1);
            hu[sp] = pk(o0 * fast_tanh(cn0), o1 * fast_tanh(cn1));
        }
        ulonglong2* hw = (ulonglong2*)(hn + j * HP);
        hw[0] = make_ulonglong2(hu[0], hu[1]);
        hw[1] = make_ulonglong2(hu[2], hu[3]);
        __syncthreads();
        cur ^= 1;
    }

    const float* hf = s_h + cur * HH * HP;
    for (int i = j; i < NB * HH; i += 128) {
        int s = i >> 7, k = i & 127;
        h_out[(long)(seq0 + s) * HH + k] = hf[k * HP + s];
    }
}

// ---------------- conv1: sparse social grid, weights staged in smem -----------
__global__ __launch_bounds__(256) void conv1_kernel(
    const float* __restrict__ w1, const float* __restrict__ b1)
{
    extern __shared__ float sm[];
    float* s_v = sm;                 // 8*9*132
    float* s_w = sm + 8 * 9 * 132;   // 32*9*132
    const int tid = threadIdx.x;
    const int b0 = blockIdx.x * 8;

    for (int i = tid; i < 8 * 9 * 128; i += 256) {
        int b = i / 1152, r = i % 1152, cell = r >> 7, c = r & 127;
        float v = (cell == 0) ? g_ht[(b0 + b) * HH + c]
                              : g_hn[((b0 + b) * KN + cell - 1) * HH + c];
        s_v[(b * 9 + cell) * 132 + c] = v;
    }

    const int o = tid >> 3, b = tid & 7;
    const float* vb = s_v + b * 1188;

    for (int half = 0; half < 2; half++) {
        __syncthreads();
        for (int i = tid; i < 32 * 1152; i += 256) {
            int oo = i / 1152, r = i % 1152, c = r / 9, tap = r % 9;
            s_w[oo * 1188 + tap * 132 + c] = w1[half * 32 * 1152 + i];
        }
        __syncthreads();

        const int och = half * 32 + o;
        const float bias = __ldg(b1 + och);
        const float* wb = s_w + o * 1188;
        const int CY[9] = {4, 0, 0, 0, 0, 0, 0, 0, 1};
        const int CX[9] = {4, 1, 2, 3, 4, 5, 6, 7, 0};

        for (int p = 0; p < 8; p++) {
            u64 acc[8];
#pragma unroll
            for (int q = 0; q < 8; q++) acc[q] = pk(bias, 0.f);
#pragma unroll
            for (int ci = 0; ci < 9; ci++) {
                const int cx = CX[ci];
                int dy = CY[ci] - p;
                if (dy < -1 || dy > 1) continue;
                const ulonglong2* vp  = (const ulonglong2*)(vb + ci * 132);
                const ulonglong2* wL  = (const ulonglong2*)(wb + ((dy + 1) * 3 + 2) * 132);
                const ulonglong2* wC  = (const ulonglong2*)(wb + ((dy + 1) * 3 + 1) * 132);
                const ulonglong2* wR  = (const ulonglong2*)(wb + ((dy + 1) * 3 + 0) * 132);
#pragma unroll 8
                for (int cc = 0; cc < 32; cc++) {
                    ulonglong2 vv = vp[cc];
                    if (cx - 1 >= 0) {
                        ulonglong2 wv = wL[cc];
                        fma2(acc[cx - 1], wv.x, vv.x);
                        fma2(acc[cx - 1], wv.y, vv.y);
                    }
                    {
                        ulonglong2 wv = wC[cc];
                        fma2(acc[cx], wv.x, vv.x);
                        fma2(acc[cx], wv.y, vv.y);
                    }
                    if (cx + 1 <= 7) {
                        ulonglong2 wv = wR[cc];
                        fma2(acc[cx + 1], wv.x, vv.x);
                        fma2(acc[cx + 1], wv.y, vv.y);
                    }
                }
            }
            float oq[8];
#pragma unroll
            for (int q = 0; q < 8; q++) oq[q] = fmaxf(upsum(acc[q]), 0.f);
            float4* dst = (float4*)(g_y1 + ((long)(b0 + b) * 64 + och) * 64 + p * 8);
            dst[0] = make_float4(oq[0], oq[1], oq[2], oq[3]);
            dst[1] = make_float4(oq[4], oq[5], oq[6], oq[7]);
        }
    }
}

// ---------------- conv2 + relu + maxpool ---------------------------------------
__global__ __launch_bounds__(256) void conv2_kernel(
    const float* __restrict__ w2, const float* __restrict__ b2)
{
    extern __shared__ float sm[];
    float* s_y = sm;                 // 8192
    float* s_w = sm + 8192;          // 32*577
    const int tid = threadIdx.x;
    const int b0 = blockIdx.x * 2;

    for (int i = tid; i < 8192; i += 256) s_y[i] = g_y1[(long)b0 * 4096 + i];
    for (int i = tid; i < 32 * 576; i += 256) {
        int c2 = i / 576, r = i % 576;
        s_w[c2 * 577 + r] = w2[i];
    }
    __syncthreads();

    const int b  = tid >> 7;
    const int cp = (tid >> 3) & 15;
    const int p  = tid & 7;
    const int c2a = cp, c2b = cp + 16;

    u64 acca[4], accb[4];
#pragma unroll
    for (int m = 0; m < 4; m++) { acca[m] = 0ull; accb[m] = 0ull; }

    for (int ty = 0; ty < 3; ty++) {
        int ip = p + ty - 1;
        if (ip < 0 || ip > 7) continue;
        for (int c1 = 0; c1 < 64; c1++) {
            const float4* yr = (const float4*)(s_y + ((b * 64 + c1) * 64 + ip * 8));
            float4 a0 = yr[0], a1 = yr[1];
            u64 C0 = pk(a0.x, a0.y), C1 = pk(a0.z, a0.w);
            u64 C2 = pk(a1.x, a1.y), C3 = pk(a1.z, a1.w);
            u64 L0 = pk(0.f,  a0.x), L1 = pk(a0.y, a0.z);
            u64 L2 = pk(a0.w, a1.x), L3 = pk(a1.y, a1.z);
            u64 R3 = pk(a1.w, 0.f);
            const float* wpa = s_w + c2a * 577 + c1 * 9 + ty * 3;
            const float* wpb = s_w + c2b * 577 + c1 * 9 + ty * 3;
            u64 W0a = pk(wpa[0], wpa[0]), W1a = pk(wpa[1], wpa[1]), W2a = pk(wpa[2], wpa[2]);
            u64 W0b = pk(wpb[0], wpb[0]), W1b = pk(wpb[1], wpb[1]), W2b = pk(wpb[2], wpb[2]);
            fma2(acca[0], W1a, C0); fma2(acca[1], W1a, C1);
            fma2(acca[2], W1a, C2); fma2(acca[3], W1a, C3);
            fma2(acca[0], W0a, L0); fma2(acca[1], W0a, L1);
            fma2(acca[2], W0a, L2); fma2(acca[3], W0a, L3);
            fma2(acca[0], W2a, L1); fma2(acca[1], W2a, L2);
            fma2(acca[2], W2a, L3); fma2(acca[3], W2a, R3);
            fma2(accb[0], W1b, C0); fma2(accb[1], W1b, C1);
            fma2(accb[2], W1b, C2); fma2(accb[3], W1b, C3);
            fma2(accb[0], W0b, L0); fma2(accb[1], W0b, L1);
            fma2(accb[2], W0b, L2); fma2(accb[3], W0b, L3);
            fma2(accb[0], W2b, L1); fma2(accb[1], W2b, L2);
            fma2(accb[2], W2b, L3); fma2(accb[3], W2b, R3);
        }
    }
    float bia = __ldg(b2 + c2a), bib = __ldg(b2 + c2b);
    float ma = 0.f, mb = 0.f;
#pragma unroll
    for (int m = 0; m < 4; m++) {
        float2 fa = up2(acca[m]);
        float2 fb = up2(accb[m]);
        ma = fmaxf(ma, fmaxf(fa.x, fa.y) + bia);
        mb = fmaxf(mb, fmaxf(fb.x, fb.y) + bib);
    }
    for (int off = 4; off; off >>= 1) {
        ma = fmaxf(ma, __shfl_xor_sync(0xffffffffu, ma, off));
        mb = fmaxf(mb, __shfl_xor_sync(0xffffffffu, mb, off));
    }
    if (p == 0) {
        g_pool[(b0 + b) * 32 + c2a] = ma;
        g_pool[(b0 + b) * 32 + c2b] = mb;
    }
}

// ---------------- fusion --------------------------------------------------------
__global__ __launch_bounds__(512) void fuse_kernel(
    const float* __restrict__ fw, const float* __restrict__ fb)
{
    extern __shared__ float sm[];
    float* s_w = sm;                 // 128*161
    float* s_in = sm + 128 * 161;    // 32*160
    const int tid = threadIdx.x;
    const int b0 = blockIdx.x * 32;

    for (int i = tid; i < 128 * 160; i += 512) {
        int r = i / 160, c = i % 160;
        s_w[r * 161 + c] = fw[i];
    }
    for (int i = tid; i < 32 * 160; i += 512) {
        int s = i / 160, c = i % 160;
        s_in[i] = (c < 128) ? g_ht[(b0 + s) * HH + c] : g_pool[(b0 + s) * 32 + (c - 128)];
    }
    __syncthreads();

    const int g = tid >> 7, j = tid & 127;
    float acc[8];
    float bias = __ldg(fb + j);
#pragma unroll
    for (int ss = 0; ss < 8; ss++) acc[ss] = bias;
    for (int k = 0; k < 160; k++) {
        float w = s_w[j * 161 + k];
#pragma unroll
        for (int ss = 0; ss < 8; ss++)
            acc[ss] = fmaf(w, s_in[(g * 8 + ss) * 160 + k], acc[ss]);
    }
#pragma unroll
    for (int ss = 0; ss < 8; ss++)
        g_fused[(b0 + g * 8 + ss) * HH + j] = fast_tanh(acc[ss]);
}

// ---------------- decoder: 4 rows/thread, NB=8 ---------------------------------
__global__ __launch_bounds__(128, 4) void dec_kernel(
    const float* __restrict__ w_ih,
    const float* __restrict__ b_ih, const float* __restrict__ b_hh,
    const float* __restrict__ out_w, const float* __restrict__ out_b,
    float* __restrict__ out)
{
    extern __shared__ float sm[];
    float* s_h   = sm;                 // 2*128*HP = 3072
    float* s_inp = s_h + 2 * HH * HP;  // 16
    float* s_ow  = s_inp + 16;         // 256

    const int j = threadIdx.x;
    const int b0 = blockIdx.x * NB;

    for (int i = j; i < NB * HH; i += 128) {
        int s = i >> 7, k = i & 127;
        s_h[k * HP + s] = g_fused[(long)b0 * HH + i];
    }
    if (j < 16) s_inp[j] = 0.f;
    for (int i = j; i < 256; i += 128) s_ow[i] = out_w[i];
    __syncthreads();

    float bbv[4], wiA[4], wiB[4];
#pragma unroll
    for (int r = 0; r < 4; r++) {
        int row = r * HH + j;
        bbv[r] = b_ih[row] + b_hh[row];
        wiA[r] = w_ih[row * 2];
        wiB[r] = w_ih[row * 2 + 1];
    }
    const float ob = out_b[j & 1];
    u64 c2[SP];
#pragma unroll
    for (int sp = 0; sp < SP; sp++) c2[sp] = 0ull;

    const float4* wt4 = (const float4*)g_wtd;
    int cur = 0;
    u64 hu[SP];

    for (int t = 0; t < PRED; t++) {
        const float* hc = s_h + cur * HH * HP;
        float* hn = s_h + (cur ^ 1) * HH * HP;

        u64 acc[4][SP];
#pragma unroll
        for (int sp = 0; sp < SP; sp++) {
            float a0 = s_inp[4 * sp + 0], a1 = s_inp[4 * sp + 1];
            float b0v = s_inp[4 * sp + 2], b1v = s_inp[4 * sp + 3];
#pragma unroll
            for (int r = 0; r < 4; r++) {
                float A = fmaf(wiB[r], a1, fmaf(wiA[r], a0, bbv[r]));
                float B = fmaf(wiB[r], b1v, fmaf(wiA[r], b0v, bbv[r]));
                acc[r][sp] = pk(A, B);
            }
        }

        const ulonglong2* h2 = (const ulonglong2*)hc;
#define KSTEP(CMP, KOFF) { \
            const ulonglong2* hb = h2 + ((kk << 2) + (KOFF)) * (HP / 4); \
            ulonglong2 hA = hb[0], hB = hb[1]; \
            u64 hp[SP] = {hA.x, hA.y, hB.x, hB.y}; \
            u64 W0 = pk(qa.CMP, qa.CMP), W1 = pk(qb.CMP, qb.CMP); \
            u64 W2 = pk(qc.CMP, qc.CMP), W3 = pk(qd.CMP, qd.CMP); \
            _Pragma("unroll") \
            for (int sp = 0; sp < SP; sp++) { \
                fma2(acc[0][sp], W0, hp[sp]); \
                fma2(acc[1][sp], W1, hp[sp]); \
                fma2(acc[2][sp], W2, hp[sp]); \
                fma2(acc[3][sp], W3, hp[sp]); \
            } }

        for (int kk = 0; kk < 32; kk++) {
            float4 qa = wt4[(kk << 9) + j];
            float4 qb = wt4[(kk << 9) + j + 128];
            float4 qc = wt4[(kk << 9) + j + 256];
            float4 qd = wt4[(kk << 9) + j + 384];
            KSTEP(x, 0) KSTEP(y, 1) KSTEP(z, 2) KSTEP(w, 3)
        }
#undef KSTEP

#pragma unroll
        for (int sp = 0; sp < SP; sp++) {
            float2 xi = up2(acc[0][sp]);
            float2 xf = up2(acc[1][sp]);
            float2 xg = up2(acc[2][sp]);
            float2 xo = up2(acc[3][sp]);
            float i0 = fast_sig(xi.x), i1 = fast_sig(xi.y);
            float f0 = fast_sig(xf.x), f1 = fast_sig(xf.y);
            float g0 = fast_tanh(xg.x), g1 = fast_tanh(xg.y);
            float o0 = fast_sig(xo.x), o1 = fast_sig(xo.y);
            float2 cc = up2(c2[sp]);
            float cn0 = fmaf(f0, cc.x, i0 * g0);
            float cn1 = fmaf(f1, cc.y, i1 * g1);
            c2[sp] = pk(cn0, cn1);
            hu[sp] = pk(o0 * fast_tanh(cn0), o1 * fast_tanh(cn1));
        }
        ulonglong2* hw = (ulonglong2*)(hn + j * HP);
        hw[0] = make_ulonglong2(hu[0], hu[1]);
        hw[1] = make_ulonglong2(hu[2], hu[3]);
        __syncthreads();
        cur ^= 1;

        if (j < 16) {
            int s = j >> 1, d = j & 1;
            const float* hw2 = s_ow + d * HH;
            const float* hh = s_h + cur * HH * HP;
            float psum = ob;
#pragma unroll 8
            for (int k = 0; k < HH; k++) psum = fmaf(hw2[k], hh[k * HP + s], psum);
            out[(long)(b0 + s) * (PRED * 2) + t * 2 + d] = psum;
            s_inp[s * 2 + d] = psum;
        }
        __syncthreads();
    }
}

// ---------------- launch ---------------------------------------------------------
extern "C" void kernel_launch(void* const* d_in, const int* in_sizes, int n_in,
                              void* d_out, int out_size)
{
    const float* target  = (const float*)d_in[0];
    const float* neigh   = (const float*)d_in[1];
    const float* enc_w_ih = (const float*)d_in[4];
    const float* enc_w_hh = (const float*)d_in[5];
    const float* enc_b_ih = (const float*)d_in[6];
    const float* enc_b_hh = (const float*)d_in[7];
    const float* nb_w_ih  = (const float*)d_in[8];
    const float* nb_w_hh  = (const float*)d_in[9];
    const float* nb_b_ih  = (const float*)d_in[10];
    const float* nb_b_hh  = (const float*)d_in[11];
    const float* conv1_w  = (const float*)d_in[12];
    const float* conv1_b  = (const float*)d_in[13];
    const float* conv2_w  = (const float*)d_in[14];
    const float* conv2_b  = (const float*)d_in[15];
    const float* fus_w    = (const float*)d_in[16];
    const float* fus_b    = (const float*)d_in[17];
    const float* dec_w_ih = (const float*)d_in[18];
    const float* dec_w_hh = (const float*)d_in[19];
    const float* dec_b_ih = (const float*)d_in[20];
    const float* dec_b_hh = (const float*)d_in[21];
    const float* out_w    = (const float*)d_in[22];
    const float* out_b    = (const float*)d_in[23];
    float* out = (float*)d_out;

    const int ENC_SMEM  = (NB * TT * FF + 2 * HH * HP + 4 * HH * FF + 512) * 4;
    const int C1_SMEM   = (8 * 9 * 132 + 32 * 9 * 132) * 4;
    const int C2_SMEM   = (8192 + 32 * 577) * 4;
    const int FUSE_SMEM = (128 * 161 + 32 * 160) * 4;
    const int DEC_SMEM  = (2 * HH * HP + 16 + 256) * 4;

    cudaFuncSetAttribute(enc_kernel,  cudaFuncAttributeMaxDynamicSharedMemorySize, ENC_SMEM);
    cudaFuncSetAttribute(conv1_kernel, cudaFuncAttributeMaxDynamicSharedMemorySize, C1_SMEM);
    cudaFuncSetAttribute(conv2_kernel, cudaFuncAttributeMaxDynamicSharedMemorySize, C2_SMEM);
    cudaFuncSetAttribute(fuse_kernel, cudaFuncAttributeMaxDynamicSharedMemorySize, FUSE_SMEM);
    cudaFuncSetAttribute(dec_kernel,  cudaFuncAttributeMaxDynamicSharedMemorySize, DEC_SMEM);

    float* d_wte; cudaGetSymbolAddress((void**)&d_wte, g_wte);
    float* d_wtn; cudaGetSymbolAddress((void**)&d_wtn, g_wtn);
    float* d_wtd; cudaGetSymbolAddress((void**)&d_wtd, g_wtd);

    transpose_kernel<<<256, 256>>>(enc_w_hh, d_wte);
    transpose_kernel<<<256, 256>>>(nb_w_hh,  d_wtn);
    transpose_kernel<<<256, 256>>>(dec_w_hh, d_wtd);

    // merged encoders: 1024 target blocks + 8192 neighbor blocks
    enc_kernel<<<TBLK + BATCH * KN / NB, 128, ENC_SMEM>>>(
        target, neigh, enc_w_ih, nb_w_ih,
        enc_b_ih, enc_b_hh, nb_b_ih, nb_b_hh);

    conv1_kernel<<<BATCH / 8, 256, C1_SMEM>>>(conv1_w, conv1_b);
    conv2_kernel<<<BATCH / 2, 256, C2_SMEM>>>(conv2_w, conv2_b);
    fuse_kernel<<<BATCH / 32, 512, FUSE_SMEM>>>(fus_w, fus_b);
    dec_kernel<<<BATCH / NB, 128, DEC_SMEM>>>(dec_w_ih, dec_b_ih, dec_b_hh,
                                              out_w, out_b, out);
}